// round 1
// baseline (speedup 1.0000x reference)
#include <cuda_runtime.h>

#define NN 74240
#define EE 593920
#define DIN 75
#define DD 128
#define NLAYERS 3
#define EPS_BN 1e-5f

// -------- scratch (no allocation allowed; device globals are the sanctioned path) ----
__device__ float g_h[NN * DD];     // current node embedding
__device__ float g_agg[NN * DD];   // segment-sum result
__device__ float g_tmp[NN * DD];   // pre-BN h2
__device__ float g_sum[DD];
__device__ float g_sumsq[DD];

// ============================================================================
// init GEMM: g_h = X[NN,75] @ W[75,128]
// CTA: 128 rows x 128 cols, 256 threads, 8x8 micro-tile, K chunked by 25.
// ============================================================================
__global__ void __launch_bounds__(256) k_init_gemm(const float* __restrict__ X,
                                                   const float* __restrict__ W) {
    __shared__ float Xs[128 * 27];   // stride 27 (row diff 8 -> bank offset 24, no conflicts)
    __shared__ float Ws[25 * 128];

    int tid = threadIdx.x;
    int tx = tid & 15, ty = tid >> 4;
    int rowBase = blockIdx.x * 128;

    float acc[8][8];
#pragma unroll
    for (int i = 0; i < 8; i++)
#pragma unroll
        for (int j = 0; j < 8; j++) acc[i][j] = 0.f;

    for (int k0 = 0; k0 < 75; k0 += 25) {
        for (int idx = tid; idx < 128 * 25; idx += 256) {
            int r = idx / 25, k = idx - r * 25;
            Xs[r * 27 + k] = X[(rowBase + r) * 75 + k0 + k];
        }
        for (int idx = tid; idx < 25 * 128; idx += 256) {
            int k = idx >> 7, c = idx & 127;
            Ws[k * 128 + c] = W[(k0 + k) * 128 + c];
        }
        __syncthreads();

#pragma unroll 5
        for (int k = 0; k < 25; k++) {
            float b[8];
            float4 b0 = *(const float4*)&Ws[k * 128 + tx * 8];
            float4 b1 = *(const float4*)&Ws[k * 128 + tx * 8 + 4];
            b[0] = b0.x; b[1] = b0.y; b[2] = b0.z; b[3] = b0.w;
            b[4] = b1.x; b[5] = b1.y; b[6] = b1.z; b[7] = b1.w;
            float a[8];
#pragma unroll
            for (int i = 0; i < 8; i++) a[i] = Xs[(ty * 8 + i) * 27 + k];
#pragma unroll
            for (int i = 0; i < 8; i++)
#pragma unroll
                for (int j = 0; j < 8; j++) acc[i][j] += a[i] * b[j];
        }
        __syncthreads();
    }

#pragma unroll
    for (int i = 0; i < 8; i++) {
        int r = rowBase + ty * 8 + i;
        *(float4*)&g_h[r * 128 + tx * 8]     = make_float4(acc[i][0], acc[i][1], acc[i][2], acc[i][3]);
        *(float4*)&g_h[r * 128 + tx * 8 + 4] = make_float4(acc[i][4], acc[i][5], acc[i][6], acc[i][7]);
    }
}

// ============================================================================
// 128x128 GEMM + bias + ReLU, optional accumulate into C:
//   accum=0 : C = relu(A@W + bias)
//   accum=1 : C = C + relu(A@W + bias)
// ============================================================================
__global__ void __launch_bounds__(256) k_gemm_relu(const float* __restrict__ A,
                                                   const float* __restrict__ W,
                                                   const float* __restrict__ bias,
                                                   float* __restrict__ C,
                                                   int accum) {
    __shared__ float As[128 * 33];   // stride 33: row diff 8 -> bank offset 8, conflict-free
    __shared__ float Ws[32 * 128];
    __shared__ float bs[128];

    int tid = threadIdx.x;
    int tx = tid & 15, ty = tid >> 4;
    int rowBase = blockIdx.x * 128;

    if (tid < 128) bs[tid] = bias[tid];

    float acc[8][8];
#pragma unroll
    for (int i = 0; i < 8; i++)
#pragma unroll
        for (int j = 0; j < 8; j++) acc[i][j] = 0.f;

    for (int k0 = 0; k0 < 128; k0 += 32) {
        // A tile: 128 rows x 32 k (float4 global loads, scalar smem stores for stride 33)
        for (int idx = tid; idx < 1024; idx += 256) {
            int r = idx >> 3, q = idx & 7;
            float4 v = *(const float4*)&A[(rowBase + r) * 128 + k0 + q * 4];
            float* p = &As[r * 33 + q * 4];
            p[0] = v.x; p[1] = v.y; p[2] = v.z; p[3] = v.w;
        }
        // W tile: 32 k x 128 cols
        for (int idx = tid; idx < 1024; idx += 256) {
            int k = idx >> 5, qc = idx & 31;
            float4 v = *(const float4*)&W[(k0 + k) * 128 + qc * 4];
            *(float4*)&Ws[k * 128 + qc * 4] = v;
        }
        __syncthreads();

#pragma unroll 4
        for (int k = 0; k < 32; k++) {
            float b[8];
            float4 b0 = *(const float4*)&Ws[k * 128 + tx * 8];
            float4 b1 = *(const float4*)&Ws[k * 128 + tx * 8 + 4];
            b[0] = b0.x; b[1] = b0.y; b[2] = b0.z; b[3] = b0.w;
            b[4] = b1.x; b[5] = b1.y; b[6] = b1.z; b[7] = b1.w;
            float a[8];
#pragma unroll
            for (int i = 0; i < 8; i++) a[i] = As[(ty * 8 + i) * 33 + k];
#pragma unroll
            for (int i = 0; i < 8; i++)
#pragma unroll
                for (int j = 0; j < 8; j++) acc[i][j] += a[i] * b[j];
        }
        __syncthreads();
    }

#pragma unroll
    for (int i = 0; i < 8; i++) {
        int r = rowBase + ty * 8 + i;
        float* cp = &C[r * 128 + tx * 8];
        float o[8];
#pragma unroll
        for (int j = 0; j < 8; j++) {
            float v = acc[i][j] + bs[tx * 8 + j];
            o[j] = v > 0.f ? v : 0.f;
        }
        if (accum) {
            float4 c0 = *(const float4*)cp;
            float4 c1 = *(const float4*)(cp + 4);
            o[0] += c0.x; o[1] += c0.y; o[2] += c0.z; o[3] += c0.w;
            o[4] += c1.x; o[5] += c1.y; o[6] += c1.z; o[7] += c1.w;
        }
        *(float4*)cp       = make_float4(o[0], o[1], o[2], o[3]);
        *(float4*)(cp + 4) = make_float4(o[4], o[5], o[6], o[7]);
    }
}

// ============================================================================
// zero agg buffer (+ BN stat accumulators)
// ============================================================================
__global__ void k_zero_agg() {
    int idx = blockIdx.x * blockDim.x + threadIdx.x;
    if (idx * 4 < NN * DD)
        *(float4*)&g_agg[idx * 4] = make_float4(0.f, 0.f, 0.f, 0.f);
    if (blockIdx.x == 0 && threadIdx.x < DD) {
        g_sum[threadIdx.x] = 0.f;
        g_sumsq[threadIdx.x] = 0.f;
    }
}

// ============================================================================
// edge scatter: agg[dst] += h[src].  One warp per edge, float4 gather,
// 4 scalar fp32 atomics per lane (safe baseline; v4 RED is the next lever).
// ============================================================================
__global__ void __launch_bounds__(256) k_scatter(const float* __restrict__ h,
                                                 const int* __restrict__ src,
                                                 const int* __restrict__ dst) {
    int gid = blockIdx.x * blockDim.x + threadIdx.x;
    int e = gid >> 5;
    if (e >= EE) return;
    int lane = gid & 31;
    int s = __ldg(&src[e]);
    int d = __ldg(&dst[e]);
    float4 v = *(const float4*)&h[s * 128 + lane * 4];
    float* o = &g_agg[d * 128 + lane * 4];
    atomicAdd(o + 0, v.x);
    atomicAdd(o + 1, v.y);
    atomicAdd(o + 2, v.z);
    atomicAdd(o + 3, v.w);
}

// ============================================================================
// BN column statistics over g_tmp: per-block register partials -> 580 atomics/col
// ============================================================================
__global__ void __launch_bounds__(128) k_bn_stats(const float* __restrict__ x) {
    int c = threadIdx.x;
    float s = 0.f, ss = 0.f;
    for (int r = blockIdx.x; r < NN; r += 580) {
        float v = x[r * 128 + c];
        s += v;
        ss += v * v;
    }
    atomicAdd(&g_sum[c], s);
    atomicAdd(&g_sumsq[c], ss);
}

// ============================================================================
// BN normalize: out = gamma*(x-mu)*rsqrt(var+eps)+beta
// ============================================================================
__global__ void __launch_bounds__(256) k_bn_norm(const float* __restrict__ x,
                                                 float* __restrict__ out,
                                                 const float* __restrict__ gamma,
                                                 const float* __restrict__ beta) {
    int idx = blockIdx.x * blockDim.x + threadIdx.x;
    int base = idx * 4;
    if (base >= NN * DD) return;
    int c = base & 127;
    const float invN = 1.f / (float)NN;
    float4 v = *(const float4*)&x[base];
    float xv[4] = {v.x, v.y, v.z, v.w};
    float o[4];
#pragma unroll
    for (int j = 0; j < 4; j++) {
        float mu = g_sum[c + j] * invN;
        float var = g_sumsq[c + j] * invN - mu * mu;
        float rs = rsqrtf(var + EPS_BN);
        o[j] = gamma[c + j] * (xv[j] - mu) * rs + beta[c + j];
    }
    *(float4*)&out[base] = make_float4(o[0], o[1], o[2], o[3]);
}

// ============================================================================
extern "C" void kernel_launch(void* const* d_in, const int* in_sizes, int n_in,
                              void* d_out, int out_size) {
    const float* X     = (const float*)d_in[0];
    const int*   src   = (const int*)d_in[1];
    const int*   dst   = (const int*)d_in[2];
    const float* Winit = (const float*)d_in[3];
    const float* Wg    = (const float*)d_in[4];
    const float* bg    = (const float*)d_in[5];
    const float* Wr    = (const float*)d_in[6];
    const float* br    = (const float*)d_in[7];
    const float* gamma = (const float*)d_in[8];
    const float* beta  = (const float*)d_in[9];
    float* out = (float*)d_out;

    void *ph, *pagg, *ptmp;
    cudaGetSymbolAddress(&ph, g_h);
    cudaGetSymbolAddress(&pagg, g_agg);
    cudaGetSymbolAddress(&ptmp, g_tmp);
    float* h   = (float*)ph;
    float* agg = (float*)pagg;
    float* tmp = (float*)ptmp;

    const int gemmGrid = NN / 128;          // 580
    const int zeroGrid = (NN * DD / 4 + 255) / 256;   // 9280
    const int scatGrid = (EE * 32) / 256;   // 74240

    k_init_gemm<<<gemmGrid, 256>>>(X, Winit);

    for (int l = 0; l < NLAYERS; l++) {
        k_zero_agg<<<zeroGrid, 256>>>();
        k_scatter<<<scatGrid, 256>>>(h, src, dst);
        k_gemm_relu<<<gemmGrid, 256>>>(agg, Wg + l * DD * DD, bg + l * DD, tmp, 0);
        k_gemm_relu<<<gemmGrid, 256>>>(h,   Wr + l * DD * DD, br + l * DD, tmp, 1);
        k_bn_stats<<<gemmGrid, 128>>>(tmp);
        k_bn_norm<<<zeroGrid, 256>>>(tmp, (l == NLAYERS - 1) ? out : h,
                                     gamma + l * DD, beta + l * DD);
    }
}

// round 3
// speedup vs baseline: 1.6315x; 1.6315x over previous
#include <cuda_runtime.h>
#include <cstdint>

#define NN 74240
#define EE 593920
#define DIN 75
#define DD 128
#define NLAYERS 3
#define EPS_BN 1e-5f

// ---------------- scratch ----------------
__device__ float g_h[NN * DD];
__device__ float g_agg[NN * DD];
__device__ float g_tmp[NN * DD];
__device__ float g_sum[DD];
__device__ float g_sumsq[DD];

// ============================================================================
// init GEMM (fp32 SIMT, accuracy margin): g_h = X[NN,75] @ W[75,128]
// ============================================================================
__global__ void __launch_bounds__(256) k_init_gemm(const float* __restrict__ X,
                                                   const float* __restrict__ W) {
    __shared__ float Xs[128 * 27];
    __shared__ float Ws[25 * 128];
    int tid = threadIdx.x;
    int tx = tid & 15, ty = tid >> 4;
    int rowBase = blockIdx.x * 128;
    float acc[8][8];
#pragma unroll
    for (int i = 0; i < 8; i++)
#pragma unroll
        for (int j = 0; j < 8; j++) acc[i][j] = 0.f;

    for (int k0 = 0; k0 < 75; k0 += 25) {
        for (int idx = tid; idx < 128 * 25; idx += 256) {
            int r = idx / 25, k = idx - r * 25;
            Xs[r * 27 + k] = X[(rowBase + r) * 75 + k0 + k];
        }
        for (int idx = tid; idx < 25 * 128; idx += 256) {
            int k = idx >> 7, c = idx & 127;
            Ws[k * 128 + c] = W[(k0 + k) * 128 + c];
        }
        __syncthreads();
#pragma unroll 5
        for (int k = 0; k < 25; k++) {
            float b[8];
            float4 b0 = *(const float4*)&Ws[k * 128 + tx * 8];
            float4 b1 = *(const float4*)&Ws[k * 128 + tx * 8 + 4];
            b[0] = b0.x; b[1] = b0.y; b[2] = b0.z; b[3] = b0.w;
            b[4] = b1.x; b[5] = b1.y; b[6] = b1.z; b[7] = b1.w;
            float a[8];
#pragma unroll
            for (int i = 0; i < 8; i++) a[i] = Xs[(ty * 8 + i) * 27 + k];
#pragma unroll
            for (int i = 0; i < 8; i++)
#pragma unroll
                for (int j = 0; j < 8; j++) acc[i][j] += a[i] * b[j];
        }
        __syncthreads();
    }
#pragma unroll
    for (int i = 0; i < 8; i++) {
        int r = rowBase + ty * 8 + i;
        *(float4*)&g_h[r * 128 + tx * 8]     = make_float4(acc[i][0], acc[i][1], acc[i][2], acc[i][3]);
        *(float4*)&g_h[r * 128 + tx * 8 + 4] = make_float4(acc[i][4], acc[i][5], acc[i][6], acc[i][7]);
    }
}

// ============================================================================
// tf32 mma.sync GEMM + bias + ReLU (+ optional accumulate into C):
//   accum=0 : C = relu(A@W + bias)
//   accum=1 : C = C + relu(A@W + bias)
// CTA: 128x128, 256 threads = 8 warps (4 M-warps x 2 N-warps).
// Warp tile: 32 rows x 64 cols = 2 x 8 mma.m16n8k8 tiles per k-step.
// ============================================================================
#define AS_STRIDE 33
#define WS_STRIDE 132

__device__ __forceinline__ void mma_tf32(float* c, const uint32_t* a, const uint32_t* b) {
    asm volatile(
        "mma.sync.aligned.m16n8k8.row.col.f32.tf32.tf32.f32 "
        "{%0,%1,%2,%3}, {%4,%5,%6,%7}, {%8,%9}, {%0,%1,%2,%3};"
        : "+f"(c[0]), "+f"(c[1]), "+f"(c[2]), "+f"(c[3])
        : "r"(a[0]), "r"(a[1]), "r"(a[2]), "r"(a[3]), "r"(b[0]), "r"(b[1]));
}

__global__ void __launch_bounds__(256) k_gemm_relu_tf32(const float* __restrict__ A,
                                                        const float* __restrict__ W,
                                                        const float* __restrict__ bias,
                                                        float* __restrict__ C,
                                                        int accum) {
    __shared__ float As[128 * AS_STRIDE];
    __shared__ float Ws[32 * WS_STRIDE];
    __shared__ float bs[128];

    int tid = threadIdx.x;
    int lane = tid & 31;
    int wid = tid >> 5;
    int mwarp = wid & 3;          // 0..3 -> rows
    int nwarp = wid >> 2;         // 0..1 -> cols
    int rowBase = blockIdx.x * 128;
    int mBase = mwarp * 32;       // warp row base within CTA tile
    int nBase = nwarp * 64;       // warp col base within CTA tile

    int frow = lane >> 2;         // 0..7
    int fcol = lane & 3;          // 0..3

    if (tid < 128) bs[tid] = bias[tid];

    float acc[2][8][4];
#pragma unroll
    for (int mt = 0; mt < 2; mt++)
#pragma unroll
        for (int nt = 0; nt < 8; nt++)
#pragma unroll
            for (int j = 0; j < 4; j++) acc[mt][nt][j] = 0.f;

    for (int k0 = 0; k0 < 128; k0 += 32) {
        // load A tile [128 x 32]
        for (int idx = tid; idx < 1024; idx += 256) {
            int r = idx >> 3, q = idx & 7;
            float4 v = *(const float4*)&A[(rowBase + r) * 128 + k0 + q * 4];
            float* p = &As[r * AS_STRIDE + q * 4];
            p[0] = v.x; p[1] = v.y; p[2] = v.z; p[3] = v.w;
        }
        // load W tile [32 x 128] with k-stride 132
        for (int idx = tid; idx < 1024; idx += 256) {
            int k = idx >> 5, qc = idx & 31;
            float4 v = *(const float4*)&W[(k0 + k) * 128 + qc * 4];
            *(float4*)&Ws[k * WS_STRIDE + qc * 4] = v;
        }
        __syncthreads();

#pragma unroll
        for (int kb = 0; kb < 32; kb += 8) {
            // A fragments for the 2 M tiles
            uint32_t afrag[2][4];
#pragma unroll
            for (int mt = 0; mt < 2; mt++) {
                int r0 = mBase + mt * 16 + frow;
                afrag[mt][0] = __float_as_uint(As[r0 * AS_STRIDE + kb + fcol]);
                afrag[mt][1] = __float_as_uint(As[(r0 + 8) * AS_STRIDE + kb + fcol]);
                afrag[mt][2] = __float_as_uint(As[r0 * AS_STRIDE + kb + fcol + 4]);
                afrag[mt][3] = __float_as_uint(As[(r0 + 8) * AS_STRIDE + kb + fcol + 4]);
            }
            // B fragments for the 8 N tiles
            uint32_t bfrag[8][2];
#pragma unroll
            for (int nt = 0; nt < 8; nt++) {
                int n = nBase + nt * 8 + frow;
                bfrag[nt][0] = __float_as_uint(Ws[(kb + fcol) * WS_STRIDE + n]);
                bfrag[nt][1] = __float_as_uint(Ws[(kb + fcol + 4) * WS_STRIDE + n]);
            }
#pragma unroll
            for (int mt = 0; mt < 2; mt++)
#pragma unroll
                for (int nt = 0; nt < 8; nt++)
                    mma_tf32(acc[mt][nt], afrag[mt], bfrag[nt]);
        }
        __syncthreads();
    }

    // epilogue: C fragment layout m16n8: c0/c1 at (frow, fcol*2 +0/1), c2/c3 at (frow+8, ..)
#pragma unroll
    for (int mt = 0; mt < 2; mt++) {
#pragma unroll
        for (int nt = 0; nt < 8; nt++) {
            int col = nBase + nt * 8 + fcol * 2;
            int r0 = rowBase + mBase + mt * 16 + frow;
            int r1 = r0 + 8;
            float b0 = bs[col], b1 = bs[col + 1];
            float v0 = acc[mt][nt][0] + b0; v0 = v0 > 0.f ? v0 : 0.f;
            float v1 = acc[mt][nt][1] + b1; v1 = v1 > 0.f ? v1 : 0.f;
            float v2 = acc[mt][nt][2] + b0; v2 = v2 > 0.f ? v2 : 0.f;
            float v3 = acc[mt][nt][3] + b1; v3 = v3 > 0.f ? v3 : 0.f;
            float2* p0 = (float2*)&C[r0 * 128 + col];
            float2* p1 = (float2*)&C[r1 * 128 + col];
            if (accum) {
                float2 c0 = *p0, c1 = *p1;
                v0 += c0.x; v1 += c0.y; v2 += c1.x; v3 += c1.y;
            }
            *p0 = make_float2(v0, v1);
            *p1 = make_float2(v2, v3);
        }
    }
}

// ============================================================================
__global__ void k_zero_agg() {
    int idx = blockIdx.x * blockDim.x + threadIdx.x;
    if (idx * 4 < NN * DD)
        *(float4*)&g_agg[idx * 4] = make_float4(0.f, 0.f, 0.f, 0.f);
    if (blockIdx.x == 0 && threadIdx.x < DD) {
        g_sum[threadIdx.x] = 0.f;
        g_sumsq[threadIdx.x] = 0.f;
    }
}

// edge scatter: one warp per edge, vectorized red.global.add.v4.f32
__global__ void __launch_bounds__(256) k_scatter(const float* __restrict__ h,
                                                 const int* __restrict__ src,
                                                 const int* __restrict__ dst) {
    int gid = blockIdx.x * blockDim.x + threadIdx.x;
    int e = gid >> 5;
    if (e >= EE) return;
    int lane = gid & 31;
    int s = __ldg(&src[e]);
    int d = __ldg(&dst[e]);
    float4 v = *(const float4*)&h[s * 128 + lane * 4];
    float* o = &g_agg[d * 128 + lane * 4];
    asm volatile("red.global.add.v4.f32 [%0], {%1, %2, %3, %4};"
                 :: "l"(o), "f"(v.x), "f"(v.y), "f"(v.z), "f"(v.w) : "memory");
}

__global__ void __launch_bounds__(128) k_bn_stats(const float* __restrict__ x) {
    int c = threadIdx.x;
    float s = 0.f, ss = 0.f;
    for (int r = blockIdx.x; r < NN; r += 580) {
        float v = x[r * 128 + c];
        s += v;
        ss += v * v;
    }
    atomicAdd(&g_sum[c], s);
    atomicAdd(&g_sumsq[c], ss);
}

__global__ void __launch_bounds__(256) k_bn_norm(const float* __restrict__ x,
                                                 float* __restrict__ out,
                                                 const float* __restrict__ gamma,
                                                 const float* __restrict__ beta) {
    int idx = blockIdx.x * blockDim.x + threadIdx.x;
    int base = idx * 4;
    if (base >= NN * DD) return;
    int c = base & 127;
    const float invN = 1.f / (float)NN;
    float4 v = *(const float4*)&x[base];
    float xv[4] = {v.x, v.y, v.z, v.w};
    float o[4];
#pragma unroll
    for (int j = 0; j < 4; j++) {
        float mu = g_sum[c + j] * invN;
        float var = g_sumsq[c + j] * invN - mu * mu;
        float rs = rsqrtf(var + EPS_BN);
        o[j] = gamma[c + j] * (xv[j] - mu) * rs + beta[c + j];
    }
    *(float4*)&out[base] = make_float4(o[0], o[1], o[2], o[3]);
}

// ============================================================================
extern "C" void kernel_launch(void* const* d_in, const int* in_sizes, int n_in,
                              void* d_out, int out_size) {
    const float* X     = (const float*)d_in[0];
    const int*   src   = (const int*)d_in[1];
    const int*   dst   = (const int*)d_in[2];
    const float* Winit = (const float*)d_in[3];
    const float* Wg    = (const float*)d_in[4];
    const float* bg    = (const float*)d_in[5];
    const float* Wr    = (const float*)d_in[6];
    const float* br    = (const float*)d_in[7];
    const float* gamma = (const float*)d_in[8];
    const float* beta  = (const float*)d_in[9];
    float* out = (float*)d_out;

    void *ph, *pagg, *ptmp;
    cudaGetSymbolAddress(&ph, g_h);
    cudaGetSymbolAddress(&pagg, g_agg);
    cudaGetSymbolAddress(&ptmp, g_tmp);
    float* h   = (float*)ph;
    float* agg = (float*)pagg;
    float* tmp = (float*)ptmp;

    const int gemmGrid = NN / 128;                      // 580
    const int zeroGrid = (NN * DD / 4 + 255) / 256;     // 9280
    const int scatGrid = (EE * 32) / 256;               // 74240

    k_init_gemm<<<gemmGrid, 256>>>(X, Winit);

    for (int l = 0; l < NLAYERS; l++) {
        k_zero_agg<<<zeroGrid, 256>>>();
        k_scatter<<<scatGrid, 256>>>(h, src, dst);
        k_gemm_relu_tf32<<<gemmGrid, 256>>>(agg, Wg + l * DD * DD, bg + l * DD, tmp, 0);
        k_gemm_relu_tf32<<<gemmGrid, 256>>>(h,   Wr + l * DD * DD, br + l * DD, tmp, 1);
        k_bn_stats<<<gemmGrid, 128>>>(tmp);
        k_bn_norm<<<zeroGrid, 256>>>(tmp, (l == NLAYERS - 1) ? out : h,
                                     gamma + l * DD, beta + l * DD);
    }
}

// round 4
// speedup vs baseline: 2.1663x; 1.3277x over previous
#include <cuda_runtime.h>
#include <cstdint>

#define NN 74240
#define EE 593920
#define DIN 75
#define DD 128
#define NLAYERS 3
#define EPS_BN 1e-5f

// ---------------- scratch ----------------
__device__ float g_h[NN * DD];
__device__ float g_agg[NN * DD];
__device__ float g_tmp[NN * DD];
__device__ float g_sum[NLAYERS * DD];
__device__ float g_sumsq[NLAYERS * DD];

__device__ __forceinline__ uint32_t smem_u32(const void* p) {
    uint32_t a;
    asm("{ .reg .u64 t; cvta.to.shared.u64 t, %1; cvt.u32.u64 %0, t; }" : "=r"(a) : "l"(p));
    return a;
}
__device__ __forceinline__ void cp16(uint32_t dst, const float* src) {
    asm volatile("cp.async.cg.shared.global [%0], [%1], 16;" :: "r"(dst), "l"(src));
}
#define CP_COMMIT() asm volatile("cp.async.commit_group;" ::: "memory")
#define CP_WAIT(n)  asm volatile("cp.async.wait_group %0;" :: "n"(n) : "memory")

__device__ __forceinline__ uint32_t f2tf32(float v) {
    uint32_t u;
    asm("cvt.rna.tf32.f32 %0, %1;" : "=r"(u) : "f"(v));
    return u;
}
__device__ __forceinline__ void mma_tf32(float* c, const uint32_t* a, const uint32_t* b) {
    asm volatile(
        "mma.sync.aligned.m16n8k8.row.col.f32.tf32.tf32.f32 "
        "{%0,%1,%2,%3}, {%4,%5,%6,%7}, {%8,%9}, {%0,%1,%2,%3};"
        : "+f"(c[0]), "+f"(c[1]), "+f"(c[2]), "+f"(c[3])
        : "r"(a[0]), "r"(a[1]), "r"(a[2]), "r"(a[3]), "r"(b[0]), "r"(b[1]));
}

// ============================================================================
// init GEMM (fp32 SIMT, accuracy margin): g_h = X[NN,75] @ W[75,128]
// ============================================================================
__global__ void __launch_bounds__(256) k_init_gemm(const float* __restrict__ X,
                                                   const float* __restrict__ W) {
    __shared__ float Xs[128 * 27];
    __shared__ float Ws[25 * 128];
    int tid = threadIdx.x;
    int tx = tid & 15, ty = tid >> 4;
    int rowBase = blockIdx.x * 128;
    float acc[8][8];
#pragma unroll
    for (int i = 0; i < 8; i++)
#pragma unroll
        for (int j = 0; j < 8; j++) acc[i][j] = 0.f;

    for (int k0 = 0; k0 < 75; k0 += 25) {
        for (int idx = tid; idx < 128 * 25; idx += 256) {
            int r = idx / 25, k = idx - r * 25;
            Xs[r * 27 + k] = X[(rowBase + r) * 75 + k0 + k];
        }
        for (int idx = tid; idx < 25 * 128; idx += 256) {
            int k = idx >> 7, c = idx & 127;
            Ws[k * 128 + c] = W[(k0 + k) * 128 + c];
        }
        __syncthreads();
#pragma unroll 5
        for (int k = 0; k < 25; k++) {
            float b[8];
            float4 b0 = *(const float4*)&Ws[k * 128 + tx * 8];
            float4 b1 = *(const float4*)&Ws[k * 128 + tx * 8 + 4];
            b[0] = b0.x; b[1] = b0.y; b[2] = b0.z; b[3] = b0.w;
            b[4] = b1.x; b[5] = b1.y; b[6] = b1.z; b[7] = b1.w;
            float a[8];
#pragma unroll
            for (int i = 0; i < 8; i++) a[i] = Xs[(ty * 8 + i) * 27 + k];
#pragma unroll
            for (int i = 0; i < 8; i++)
#pragma unroll
                for (int j = 0; j < 8; j++) acc[i][j] += a[i] * b[j];
        }
        __syncthreads();
    }
#pragma unroll
    for (int i = 0; i < 8; i++) {
        int r = rowBase + ty * 8 + i;
        *(float4*)&g_h[r * 128 + tx * 8]     = make_float4(acc[i][0], acc[i][1], acc[i][2], acc[i][3]);
        *(float4*)&g_h[r * 128 + tx * 8 + 4] = make_float4(acc[i][4], acc[i][5], acc[i][6], acc[i][7]);
    }
}

// ============================================================================
// Fused layer kernel: C = relu(A1@W1+b1) + relu(A2@W2+b2)  + BN column stats
// CTA 128x128, 256 thr, 8 warps (4m x 2n). 2-stage cp.async pipeline over
// 4 k-chunks of 32. smem per stage: A1,A2 [128x32] stride 36; W1,W2 [32x128]
// stride 136. Stage = 71680 B; 2 stages + 256 bias floats = 144384 B.
// ============================================================================
#define STG_F   17920      // stage stride in floats
#define A2_F    4608
#define W1_F    9216
#define W2_F    13568
#define BIAS_F  35840
#define SMEM_FUSED 144384

struct FusedPtrs {
    const float *A1, *A2, *W1, *W2;
};

__device__ __forceinline__ void issue_chunk(uint32_t sb, int st, int c, int tid,
                                            int rowBase, const FusedPtrs& P) {
    uint32_t stb = sb + st * (STG_F * 4);
    int k0 = c * 32;
#pragma unroll
    for (int i = 0; i < 4; i++) {
        int idx = i * 256 + tid;
        int r = idx >> 3, q = idx & 7;
        cp16(stb + r * 144 + q * 16,            &P.A1[(rowBase + r) * 128 + k0 + q * 4]);
        cp16(stb + A2_F * 4 + r * 144 + q * 16, &P.A2[(rowBase + r) * 128 + k0 + q * 4]);
        int k = idx >> 5, qq = idx & 31;
        cp16(stb + W1_F * 4 + k * 544 + qq * 16, &P.W1[(k0 + k) * 128 + qq * 4]);
        cp16(stb + W2_F * 4 + k * 544 + qq * 16, &P.W2[(k0 + k) * 128 + qq * 4]);
    }
    CP_COMMIT();
}

__device__ __forceinline__ void compute_chunk(const float* smf, int st,
                                              int mBase, int nBase, int frow, int fcol,
                                              float acc1[2][8][4], float acc2[2][8][4]) {
    const float* As1 = smf + st * STG_F;
    const float* As2 = As1 + A2_F;
    const float* Ws1 = smf + st * STG_F + W1_F;
    const float* Ws2 = smf + st * STG_F + W2_F;
#pragma unroll
    for (int kb = 0; kb < 32; kb += 8) {
        uint32_t a1f[2][4], a2f[2][4];
#pragma unroll
        for (int mt = 0; mt < 2; mt++) {
            int r0 = mBase + mt * 16 + frow;
            a1f[mt][0] = f2tf32(As1[r0 * 36 + kb + fcol]);
            a1f[mt][1] = f2tf32(As1[(r0 + 8) * 36 + kb + fcol]);
            a1f[mt][2] = f2tf32(As1[r0 * 36 + kb + fcol + 4]);
            a1f[mt][3] = f2tf32(As1[(r0 + 8) * 36 + kb + fcol + 4]);
            a2f[mt][0] = f2tf32(As2[r0 * 36 + kb + fcol]);
            a2f[mt][1] = f2tf32(As2[(r0 + 8) * 36 + kb + fcol]);
            a2f[mt][2] = f2tf32(As2[r0 * 36 + kb + fcol + 4]);
            a2f[mt][3] = f2tf32(As2[(r0 + 8) * 36 + kb + fcol + 4]);
        }
        uint32_t b1f[8][2], b2f[8][2];
#pragma unroll
        for (int nt = 0; nt < 8; nt++) {
            int n = nBase + nt * 8 + frow;
            b1f[nt][0] = f2tf32(Ws1[(kb + fcol) * 136 + n]);
            b1f[nt][1] = f2tf32(Ws1[(kb + fcol + 4) * 136 + n]);
            b2f[nt][0] = f2tf32(Ws2[(kb + fcol) * 136 + n]);
            b2f[nt][1] = f2tf32(Ws2[(kb + fcol + 4) * 136 + n]);
        }
#pragma unroll
        for (int mt = 0; mt < 2; mt++)
#pragma unroll
            for (int nt = 0; nt < 8; nt++) {
                mma_tf32(acc1[mt][nt], a1f[mt], b1f[nt]);
                mma_tf32(acc2[mt][nt], a2f[mt], b2f[nt]);
            }
    }
}

__global__ void __launch_bounds__(256, 1) k_layer_fused(
    const float* __restrict__ A1, const float* __restrict__ A2,
    const float* __restrict__ W1, const float* __restrict__ W2,
    const float* __restrict__ b1, const float* __restrict__ b2,
    float* __restrict__ C, float* __restrict__ sumP, float* __restrict__ sumsqP) {
    extern __shared__ float smf[];
    uint32_t sb = smem_u32(smf);
    int tid = threadIdx.x;
    int lane = tid & 31;
    int wid = tid >> 5;
    int mwarp = wid & 3, nwarp = wid >> 2;
    int rowBase = blockIdx.x * 128;
    int mBase = mwarp * 32, nBase = nwarp * 64;
    int frow = lane >> 2, fcol = lane & 3;

    if (tid < 128) smf[BIAS_F + tid] = b1[tid];
    else           smf[BIAS_F + 128 + (tid - 128)] = b2[tid - 128];

    FusedPtrs P{A1, A2, W1, W2};

    float acc1[2][8][4], acc2[2][8][4];
#pragma unroll
    for (int mt = 0; mt < 2; mt++)
#pragma unroll
        for (int nt = 0; nt < 8; nt++)
#pragma unroll
            for (int j = 0; j < 4; j++) { acc1[mt][nt][j] = 0.f; acc2[mt][nt][j] = 0.f; }

    issue_chunk(sb, 0, 0, tid, rowBase, P);
    issue_chunk(sb, 1, 1, tid, rowBase, P);

    // c = 0
    CP_WAIT(1); __syncthreads();
    compute_chunk(smf, 0, mBase, nBase, frow, fcol, acc1, acc2);
    __syncthreads();
    issue_chunk(sb, 0, 2, tid, rowBase, P);
    // c = 1
    CP_WAIT(1); __syncthreads();
    compute_chunk(smf, 1, mBase, nBase, frow, fcol, acc1, acc2);
    __syncthreads();
    issue_chunk(sb, 1, 3, tid, rowBase, P);
    // c = 2
    CP_WAIT(1); __syncthreads();
    compute_chunk(smf, 0, mBase, nBase, frow, fcol, acc1, acc2);
    __syncthreads();
    // c = 3
    CP_WAIT(0); __syncthreads();
    compute_chunk(smf, 1, mBase, nBase, frow, fcol, acc1, acc2);

    // epilogue: bias + relu + sum, store, and BN column partial stats
    const float* bs1 = smf + BIAS_F;
    const float* bs2 = smf + BIAS_F + 128;
#pragma unroll
    for (int nt = 0; nt < 8; nt++) {
        int col = nBase + nt * 8 + fcol * 2;
        float B10 = bs1[col], B11 = bs1[col + 1];
        float B20 = bs2[col], B21 = bs2[col + 1];
        float s0 = 0.f, s1 = 0.f, q0 = 0.f, q1 = 0.f;
#pragma unroll
        for (int mt = 0; mt < 2; mt++) {
            int r0 = rowBase + mBase + mt * 16 + frow;
            int r1 = r0 + 8;
            float u0 = acc1[mt][nt][0] + B10; u0 = u0 > 0.f ? u0 : 0.f;
            float u1 = acc1[mt][nt][1] + B11; u1 = u1 > 0.f ? u1 : 0.f;
            float u2 = acc1[mt][nt][2] + B10; u2 = u2 > 0.f ? u2 : 0.f;
            float u3 = acc1[mt][nt][3] + B11; u3 = u3 > 0.f ? u3 : 0.f;
            float v0 = acc2[mt][nt][0] + B20; v0 = v0 > 0.f ? v0 : 0.f;
            float v1 = acc2[mt][nt][1] + B21; v1 = v1 > 0.f ? v1 : 0.f;
            float v2 = acc2[mt][nt][2] + B20; v2 = v2 > 0.f ? v2 : 0.f;
            float v3 = acc2[mt][nt][3] + B21; v3 = v3 > 0.f ? v3 : 0.f;
            float o0 = u0 + v0, o1 = u1 + v1, o2 = u2 + v2, o3 = u3 + v3;
            *(float2*)&C[r0 * 128 + col] = make_float2(o0, o1);
            *(float2*)&C[r1 * 128 + col] = make_float2(o2, o3);
            s0 += o0 + o2; s1 += o1 + o3;
            q0 += o0 * o0 + o2 * o2; q1 += o1 * o1 + o3 * o3;
        }
        // reduce over frow groups (lanes stride 4)
#pragma unroll
        for (int m = 4; m <= 16; m <<= 1) {
            s0 += __shfl_xor_sync(0xffffffff, s0, m);
            s1 += __shfl_xor_sync(0xffffffff, s1, m);
            q0 += __shfl_xor_sync(0xffffffff, q0, m);
            q1 += __shfl_xor_sync(0xffffffff, q1, m);
        }
        if (frow == 0) {
            atomicAdd(&sumP[col], s0);
            atomicAdd(&sumP[col + 1], s1);
            atomicAdd(&sumsqP[col], q0);
            atomicAdd(&sumsqP[col + 1], q1);
        }
    }
}

// ============================================================================
__global__ void k_zero_init() {
    int idx = blockIdx.x * blockDim.x + threadIdx.x;
    if (idx * 4 < NN * DD)
        *(float4*)&g_agg[idx * 4] = make_float4(0.f, 0.f, 0.f, 0.f);
    if (blockIdx.x == 0) {
        for (int i = threadIdx.x; i < NLAYERS * DD; i += blockDim.x) {
            g_sum[i] = 0.f;
            g_sumsq[i] = 0.f;
        }
    }
}

// edge scatter: one warp per edge, vectorized red.global.add.v4.f32
__global__ void __launch_bounds__(256) k_scatter(const float* __restrict__ h,
                                                 const int* __restrict__ src,
                                                 const int* __restrict__ dst) {
    int gid = blockIdx.x * blockDim.x + threadIdx.x;
    int e = gid >> 5;
    if (e >= EE) return;
    int lane = gid & 31;
    int s = __ldg(&src[e]);
    int d = __ldg(&dst[e]);
    float4 v = *(const float4*)&h[s * 128 + lane * 4];
    float* o = &g_agg[d * 128 + lane * 4];
    asm volatile("red.global.add.v4.f32 [%0], {%1, %2, %3, %4};"
                 :: "l"(o), "f"(v.x), "f"(v.y), "f"(v.z), "f"(v.w) : "memory");
}

// BN normalize; also re-zeroes g_agg for the next layer's scatter
__global__ void __launch_bounds__(256) k_bn_norm(const float* __restrict__ x,
                                                 float* __restrict__ out,
                                                 const float* __restrict__ gamma,
                                                 const float* __restrict__ beta,
                                                 const float* __restrict__ sumP,
                                                 const float* __restrict__ sumsqP,
                                                 int zeroAgg) {
    int idx = blockIdx.x * blockDim.x + threadIdx.x;
    int base = idx * 4;
    if (base >= NN * DD) return;
    int c = base & 127;
    const float invN = 1.f / (float)NN;
    float4 v = *(const float4*)&x[base];
    float xv[4] = {v.x, v.y, v.z, v.w};
    float o[4];
#pragma unroll
    for (int j = 0; j < 4; j++) {
        float mu = sumP[c + j] * invN;
        float var = sumsqP[c + j] * invN - mu * mu;
        float rs = rsqrtf(var + EPS_BN);
        o[j] = gamma[c + j] * (xv[j] - mu) * rs + beta[c + j];
    }
    *(float4*)&out[base] = make_float4(o[0], o[1], o[2], o[3]);
    if (zeroAgg)
        *(float4*)&g_agg[base] = make_float4(0.f, 0.f, 0.f, 0.f);
}

// ============================================================================
extern "C" void kernel_launch(void* const* d_in, const int* in_sizes, int n_in,
                              void* d_out, int out_size) {
    const float* X     = (const float*)d_in[0];
    const int*   src   = (const int*)d_in[1];
    const int*   dst   = (const int*)d_in[2];
    const float* Winit = (const float*)d_in[3];
    const float* Wg    = (const float*)d_in[4];
    const float* bg    = (const float*)d_in[5];
    const float* Wr    = (const float*)d_in[6];
    const float* br    = (const float*)d_in[7];
    const float* gamma = (const float*)d_in[8];
    const float* beta  = (const float*)d_in[9];
    float* out = (float*)d_out;

    void *ph, *pagg, *ptmp, *ps, *pq;
    cudaGetSymbolAddress(&ph, g_h);
    cudaGetSymbolAddress(&pagg, g_agg);
    cudaGetSymbolAddress(&ptmp, g_tmp);
    cudaGetSymbolAddress(&ps, g_sum);
    cudaGetSymbolAddress(&pq, g_sumsq);
    float* h    = (float*)ph;
    float* agg  = (float*)pagg;
    float* tmp  = (float*)ptmp;
    float* sum  = (float*)ps;
    float* sumq = (float*)pq;

    cudaFuncSetAttribute(k_layer_fused, cudaFuncAttributeMaxDynamicSharedMemorySize,
                         SMEM_FUSED);

    const int gemmGrid = NN / 128;                      // 580
    const int zeroGrid = (NN * DD / 4 + 255) / 256;     // 9280
    const int scatGrid = (EE * 32) / 256;               // 74240

    k_zero_init<<<zeroGrid, 256>>>();
    k_init_gemm<<<gemmGrid, 256>>>(X, Winit);

    for (int l = 0; l < NLAYERS; l++) {
        k_scatter<<<scatGrid, 256>>>(h, src, dst);
        k_layer_fused<<<gemmGrid, 256, SMEM_FUSED>>>(
            agg, h, Wg + l * DD * DD, Wr + l * DD * DD, bg + l * DD, br + l * DD,
            tmp, sum + l * DD, sumq + l * DD);
        k_bn_norm<<<zeroGrid, 256>>>(tmp, (l == NLAYERS - 1) ? out : h,
                                     gamma + l * DD, beta + l * DD,
                                     sum + l * DD, sumq + l * DD,
                                     l < NLAYERS - 1 ? 1 : 0);
    }
}

// round 5
// speedup vs baseline: 2.9846x; 1.3778x over previous
#include <cuda_runtime.h>
#include <cstdint>

#define NN 74240
#define EE 593920
#define DD 128
#define NLAYERS 3
#define EPS_BN 1e-5f

// ---------------- scratch ----------------
__device__ float g_h[NN * DD];
__device__ float g_agg[NN * DD];
__device__ float g_tmp[NN * DD];
__device__ float g_sum[NLAYERS * DD];
__device__ float g_sumsq[NLAYERS * DD];
__device__ float2 g_aff[DD];                 // per-feature BN affine (s, t)
__device__ float g_Wt[NLAYERS * 2 * DD * DD]; // transposed+rounded weights [mat][n][k]
__device__ int g_deg[NN];
__device__ int g_off[NN + 1];
__device__ int g_pos[NN];
__device__ int g_csr[EE];
__device__ int g_bsum[160];

// ---------------- helpers ----------------
__device__ __forceinline__ uint32_t smem_u32(const void* p) {
    uint32_t a;
    asm("{ .reg .u64 t; cvta.to.shared.u64 t, %1; cvt.u32.u64 %0, t; }" : "=r"(a) : "l"(p));
    return a;
}
__device__ __forceinline__ void cp16(uint32_t dst, const float* src) {
    asm volatile("cp.async.cg.shared.global [%0], [%1], 16;" :: "r"(dst), "l"(src));
}
#define CP_COMMIT() asm volatile("cp.async.commit_group;" ::: "memory")
#define CP_WAIT(n)  asm volatile("cp.async.wait_group %0;" :: "n"(n) : "memory")

__device__ __forceinline__ void ldsm_x4(uint32_t* r, uint32_t addr) {
    asm volatile("ldmatrix.sync.aligned.m8n8.x4.shared.b16 {%0,%1,%2,%3}, [%4];"
                 : "=r"(r[0]), "=r"(r[1]), "=r"(r[2]), "=r"(r[3]) : "r"(addr));
}
__device__ __forceinline__ void mma_tf32(float* c, const uint32_t* a, const uint32_t* b) {
    asm volatile(
        "mma.sync.aligned.m16n8k8.row.col.f32.tf32.tf32.f32 "
        "{%0,%1,%2,%3}, {%4,%5,%6,%7}, {%8,%9}, {%0,%1,%2,%3};"
        : "+f"(c[0]), "+f"(c[1]), "+f"(c[2]), "+f"(c[3])
        : "r"(a[0]), "r"(a[1]), "r"(a[2]), "r"(a[3]), "r"(b[0]), "r"(b[1]));
}

// ============================================================================
// weight prep: g_Wt[mat][n][k] = round_rna_tf32( W[mat][k][n] )
// ============================================================================
__global__ void __launch_bounds__(256) k_prep_w(const float* __restrict__ Wg,
                                                const float* __restrict__ Wr) {
    int gid = blockIdx.x * 256 + threadIdx.x;    // 6 * 16384 total
    int mat = gid >> 14;
    int e = gid & 16383;
    int n = e >> 7, k = e & 127;
    int l = mat >> 1, op = mat & 1;
    const float* src = (op ? Wr : Wg) + l * DD * DD;
    float v = src[k * 128 + n];
    uint32_t u;
    asm("cvt.rna.tf32.f32 %0, %1;" : "=r"(u) : "f"(v));
    g_Wt[mat * 16384 + n * 128 + k] = __uint_as_float(u);
}

// ============================================================================
// CSR build: zero -> hist -> scan1 -> scan2 -> scan3 -> fill
// ============================================================================
__global__ void __launch_bounds__(256) k_zero() {
    int i = blockIdx.x * 256 + threadIdx.x;
    if (i < NN) g_deg[i] = 0;
    if (i < NLAYERS * DD) { g_sum[i] = 0.f; g_sumsq[i] = 0.f; }
    if (i < DD) g_aff[i] = make_float2(1.f, 0.f);
}
__global__ void __launch_bounds__(256) k_hist(const int* __restrict__ dst) {
    int e = blockIdx.x * 256 + threadIdx.x;
    if (e < EE) atomicAdd(&g_deg[dst[e]], 1);
}
__global__ void __launch_bounds__(512) k_scan1() {
    __shared__ int sm[512];
    int tid = threadIdx.x;
    int i = blockIdx.x * 512 + tid;
    int v = g_deg[i];
    sm[tid] = v;
    __syncthreads();
    for (int o = 1; o < 512; o <<= 1) {
        int t = (tid >= o) ? sm[tid - o] : 0;
        __syncthreads();
        sm[tid] += t;
        __syncthreads();
    }
    g_off[i] = sm[tid] - v;                       // block-local exclusive
    if (tid == 511) g_bsum[blockIdx.x] = sm[511];
}
__global__ void __launch_bounds__(256) k_scan2() {
    __shared__ int sm[145];
    int tid = threadIdx.x;
    if (tid < 145) sm[tid] = g_bsum[tid];
    __syncthreads();
    if (tid == 0) {
        int run = 0;
        for (int b = 0; b < 145; b++) { int t = sm[b]; sm[b] = run; run += t; }
    }
    __syncthreads();
    if (tid < 145) g_bsum[tid] = sm[tid];
}
__global__ void __launch_bounds__(256) k_scan3() {
    int i = blockIdx.x * 256 + threadIdx.x;
    if (i < NN) {
        int o = g_off[i] + g_bsum[i >> 9];
        g_off[i] = o;
        g_pos[i] = o;
    }
    if (i == 0) g_off[NN] = EE;
}
__global__ void __launch_bounds__(256) k_fill(const int* __restrict__ src,
                                              const int* __restrict__ dst) {
    int e = blockIdx.x * 256 + threadIdx.x;
    if (e < EE) {
        int p = atomicAdd(&g_pos[dst[e]], 1);
        g_csr[p] = src[e];
    }
}

// ============================================================================
// gather: agg[d] = s * sum_{src in-edges} in[src] + deg * t  (BN folded)
// one warp per node; indices prefetched per 32, shfl-broadcast.
// ============================================================================
__global__ void __launch_bounds__(256) k_gather(const float* __restrict__ in) {
    int gid = blockIdx.x * 256 + threadIdx.x;
    int node = gid >> 5, lane = gid & 31;
    if (node >= NN) return;
    int beg = g_off[node], end = g_off[node + 1];
    float4 acc = make_float4(0.f, 0.f, 0.f, 0.f);
    for (int base = beg; base < end; base += 32) {
        int i = base + lane;
        int idx = (i < end) ? __ldg(&g_csr[i]) : 0;
        int cnt = min(32, end - base);
        for (int j = 0; j < cnt; j++) {
            int s = __shfl_sync(0xffffffff, idx, j);
            float4 v = *(const float4*)&in[s * 128 + lane * 4];
            acc.x += v.x; acc.y += v.y; acc.z += v.z; acc.w += v.w;
        }
    }
    float deg = (float)(end - beg);
    float2 a0 = g_aff[lane * 4], a1 = g_aff[lane * 4 + 1];
    float2 a2 = g_aff[lane * 4 + 2], a3 = g_aff[lane * 4 + 3];
    float4 o;
    o.x = a0.x * acc.x + deg * a0.y;
    o.y = a1.x * acc.y + deg * a1.y;
    o.z = a2.x * acc.z + deg * a2.y;
    o.w = a3.x * acc.w + deg * a3.y;
    *(float4*)&g_agg[node * 128 + lane * 4] = o;
}

// ============================================================================
// affine from stats: s = gamma*rsqrt(var+eps), t = beta - mu*s
// ============================================================================
__global__ void k_affine(const float* __restrict__ sumP, const float* __restrict__ sumsqP,
                         const float* __restrict__ gamma, const float* __restrict__ beta) {
    int c = threadIdx.x;
    const float invN = 1.f / (float)NN;
    float mu = sumP[c] * invN;
    float var = sumsqP[c] * invN - mu * mu;
    float s = gamma[c] * rsqrtf(var + EPS_BN);
    g_aff[c] = make_float2(s, beta[c] - mu * s);
}

// ============================================================================
// init GEMM (fp32 SIMT): g_h = X[NN,75] @ W[75,128]
// ============================================================================
__global__ void __launch_bounds__(256) k_init_gemm(const float* __restrict__ X,
                                                   const float* __restrict__ W) {
    __shared__ float Xs[128 * 27];
    __shared__ float Ws[25 * 128];
    int tid = threadIdx.x;
    int tx = tid & 15, ty = tid >> 4;
    int rowBase = blockIdx.x * 128;
    float acc[8][8];
#pragma unroll
    for (int i = 0; i < 8; i++)
#pragma unroll
        for (int j = 0; j < 8; j++) acc[i][j] = 0.f;

    for (int k0 = 0; k0 < 75; k0 += 25) {
        for (int idx = tid; idx < 128 * 25; idx += 256) {
            int r = idx / 25, k = idx - r * 25;
            Xs[r * 27 + k] = X[(rowBase + r) * 75 + k0 + k];
        }
        for (int idx = tid; idx < 25 * 128; idx += 256) {
            int k = idx >> 7, c = idx & 127;
            Ws[k * 128 + c] = W[(k0 + k) * 128 + c];
        }
        __syncthreads();
#pragma unroll 5
        for (int k = 0; k < 25; k++) {
            float b[8];
            float4 b0 = *(const float4*)&Ws[k * 128 + tx * 8];
            float4 b1 = *(const float4*)&Ws[k * 128 + tx * 8 + 4];
            b[0] = b0.x; b[1] = b0.y; b[2] = b0.z; b[3] = b0.w;
            b[4] = b1.x; b[5] = b1.y; b[6] = b1.z; b[7] = b1.w;
            float a[8];
#pragma unroll
            for (int i = 0; i < 8; i++) a[i] = Xs[(ty * 8 + i) * 27 + k];
#pragma unroll
            for (int i = 0; i < 8; i++)
#pragma unroll
                for (int j = 0; j < 8; j++) acc[i][j] += a[i] * b[j];
        }
        __syncthreads();
    }
#pragma unroll
    for (int i = 0; i < 8; i++) {
        int r = rowBase + ty * 8 + i;
        *(float4*)&g_h[r * 128 + tx * 8]     = make_float4(acc[i][0], acc[i][1], acc[i][2], acc[i][3]);
        *(float4*)&g_h[r * 128 + tx * 8 + 4] = make_float4(acc[i][4], acc[i][5], acc[i][6], acc[i][7]);
    }
}

// ============================================================================
// Fused layer GEMM (ldmatrix tf32):
//   C = relu(A1@W1 + b1) + relu( (s*A2 + t) @ W2 + b2 )  + BN column stats
// All smem tiles [128 rows][36 floats] (32 k + 4 pad). W in gmem pre-transposed
// n-major. 2-stage cp.async pipeline over 4 k-chunks of 32.
// ============================================================================
#define TILE_B  18432
#define A2_B    18432
#define W1_B    36864
#define W2_B    55296
#define STG_B   73728
#define BIAS1_F 36864
#define BIAS2_F 36992
#define AFF_F   37120
#define SMEM_FUSED 149504

__device__ __forceinline__ void issue_chunk(uint32_t sb, int st, int c, int tid, int rowBase,
                                            const float* A1, const float* A2,
                                            const float* W1t, const float* W2t) {
    uint32_t stb = sb + st * STG_B;
    int k0 = c * 32;
#pragma unroll
    for (int i = 0; i < 4; i++) {
        int idx = i * 256 + tid;
        int r = idx >> 3, q = idx & 7;
        uint32_t soff = r * 144 + q * 16;
        int goff = k0 + q * 4;
        cp16(stb + soff,        A1 + (rowBase + r) * 128 + goff);
        cp16(stb + A2_B + soff, A2 + (rowBase + r) * 128 + goff);
        cp16(stb + W1_B + soff, W1t + r * 128 + goff);
        cp16(stb + W2_B + soff, W2t + r * 128 + goff);
    }
    CP_COMMIT();
}

__device__ __forceinline__ void compute_chunk(uint32_t sb, int st, int k0,
                                              int mBase, int nBase, int lane,
                                              const float2* affS,
                                              float acc1[2][8][4], float acc2[2][8][4]) {
    uint32_t stb = sb + st * STG_B;
    int g = lane >> 3, lr = lane & 7;
    int fcol = lane & 3;
    int arow = ((g & 1) << 3) + lr;
    int abyte = (g >> 1) << 4;
    int brow = ((g >> 1) << 3) + lr;
    int bbyte = (g & 1) << 4;

#pragma unroll
    for (int kb = 0; kb < 32; kb += 8) {
        uint32_t a1[2][4], a2[2][4];
#pragma unroll
        for (int mt = 0; mt < 2; mt++) {
            uint32_t base = stb + (uint32_t)(mBase + mt * 16 + arow) * 144 + kb * 4 + abyte;
            ldsm_x4(a1[mt], base);
            ldsm_x4(a2[mt], base + A2_B);
        }
        float2 f0 = affS[k0 + kb + fcol];
        float2 f4 = affS[k0 + kb + fcol + 4];
#pragma unroll
        for (int mt = 0; mt < 2; mt++) {
            a2[mt][0] = __float_as_uint(fmaf(f0.x, __uint_as_float(a2[mt][0]), f0.y));
            a2[mt][1] = __float_as_uint(fmaf(f0.x, __uint_as_float(a2[mt][1]), f0.y));
            a2[mt][2] = __float_as_uint(fmaf(f4.x, __uint_as_float(a2[mt][2]), f4.y));
            a2[mt][3] = __float_as_uint(fmaf(f4.x, __uint_as_float(a2[mt][3]), f4.y));
        }
        uint32_t b1[4][4], b2[4][4];
#pragma unroll
        for (int p = 0; p < 4; p++) {
            uint32_t base = stb + W1_B + (uint32_t)(nBase + p * 16 + brow) * 144 + kb * 4 + bbyte;
            ldsm_x4(b1[p], base);
            ldsm_x4(b2[p], base + (W2_B - W1_B));
        }
#pragma unroll
        for (int mt = 0; mt < 2; mt++)
#pragma unroll
            for (int p = 0; p < 4; p++) {
                mma_tf32(acc1[mt][2 * p],     a1[mt], &b1[p][0]);
                mma_tf32(acc1[mt][2 * p + 1], a1[mt], &b1[p][2]);
                mma_tf32(acc2[mt][2 * p],     a2[mt], &b2[p][0]);
                mma_tf32(acc2[mt][2 * p + 1], a2[mt], &b2[p][2]);
            }
    }
}

__global__ void __launch_bounds__(256, 1) k_layer_fused(
    const float* __restrict__ A1, const float* __restrict__ A2,
    const float* __restrict__ W1t, const float* __restrict__ W2t,
    const float* __restrict__ b1, const float* __restrict__ b2,
    float* __restrict__ C, float* __restrict__ sumP, float* __restrict__ sumsqP) {
    extern __shared__ float smf[];
    uint32_t sb = smem_u32(smf);
    int tid = threadIdx.x;
    int lane = tid & 31;
    int wid = tid >> 5;
    int mwarp = wid & 3, nwarp = wid >> 2;
    int rowBase = blockIdx.x * 128;
    int mBase = mwarp * 32, nBase = nwarp * 64;
    int frow = lane >> 2, fcol = lane & 3;

    if (tid < 128) {
        smf[BIAS1_F + tid] = b1[tid];
        smf[BIAS2_F + tid] = b2[tid];
        ((float2*)(smf + AFF_F))[tid] = g_aff[tid];
    }
    const float2* affS = (const float2*)(smf + AFF_F);

    float acc1[2][8][4], acc2[2][8][4];
#pragma unroll
    for (int mt = 0; mt < 2; mt++)
#pragma unroll
        for (int nt = 0; nt < 8; nt++)
#pragma unroll
            for (int j = 0; j < 4; j++) { acc1[mt][nt][j] = 0.f; acc2[mt][nt][j] = 0.f; }

    issue_chunk(sb, 0, 0, tid, rowBase, A1, A2, W1t, W2t);
    issue_chunk(sb, 1, 1, tid, rowBase, A1, A2, W1t, W2t);

    CP_WAIT(1); __syncthreads();
    compute_chunk(sb, 0, 0, mBase, nBase, lane, affS, acc1, acc2);
    __syncthreads();
    issue_chunk(sb, 0, 2, tid, rowBase, A1, A2, W1t, W2t);

    CP_WAIT(1); __syncthreads();
    compute_chunk(sb, 1, 32, mBase, nBase, lane, affS, acc1, acc2);
    __syncthreads();
    issue_chunk(sb, 1, 3, tid, rowBase, A1, A2, W1t, W2t);

    CP_WAIT(1); __syncthreads();
    compute_chunk(sb, 0, 64, mBase, nBase, lane, affS, acc1, acc2);
    __syncthreads();

    CP_WAIT(0); __syncthreads();
    compute_chunk(sb, 1, 96, mBase, nBase, lane, affS, acc1, acc2);

    // epilogue: bias + relu + sum, store, BN column partial stats
    const float* bs1 = smf + BIAS1_F;
    const float* bs2 = smf + BIAS2_F;
#pragma unroll
    for (int nt = 0; nt < 8; nt++) {
        int col = nBase + nt * 8 + fcol * 2;
        float B10 = bs1[col], B11 = bs1[col + 1];
        float B20 = bs2[col], B21 = bs2[col + 1];
        float s0 = 0.f, s1 = 0.f, q0 = 0.f, q1 = 0.f;
#pragma unroll
        for (int mt = 0; mt < 2; mt++) {
            int r0 = rowBase + mBase + mt * 16 + frow;
            int r1 = r0 + 8;
            float u0 = acc1[mt][nt][0] + B10; u0 = u0 > 0.f ? u0 : 0.f;
            float u1 = acc1[mt][nt][1] + B11; u1 = u1 > 0.f ? u1 : 0.f;
            float u2 = acc1[mt][nt][2] + B10; u2 = u2 > 0.f ? u2 : 0.f;
            float u3 = acc1[mt][nt][3] + B11; u3 = u3 > 0.f ? u3 : 0.f;
            float v0 = acc2[mt][nt][0] + B20; v0 = v0 > 0.f ? v0 : 0.f;
            float v1 = acc2[mt][nt][1] + B21; v1 = v1 > 0.f ? v1 : 0.f;
            float v2 = acc2[mt][nt][2] + B20; v2 = v2 > 0.f ? v2 : 0.f;
            float v3 = acc2[mt][nt][3] + B21; v3 = v3 > 0.f ? v3 : 0.f;
            float o0 = u0 + v0, o1 = u1 + v1, o2 = u2 + v2, o3 = u3 + v3;
            *(float2*)&C[r0 * 128 + col] = make_float2(o0, o1);
            *(float2*)&C[r1 * 128 + col] = make_float2(o2, o3);
            s0 += o0 + o2; s1 += o1 + o3;
            q0 += o0 * o0 + o2 * o2; q1 += o1 * o1 + o3 * o3;
        }
#pragma unroll
        for (int m = 4; m <= 16; m <<= 1) {
            s0 += __shfl_xor_sync(0xffffffff, s0, m);
            s1 += __shfl_xor_sync(0xffffffff, s1, m);
            q0 += __shfl_xor_sync(0xffffffff, q0, m);
            q1 += __shfl_xor_sync(0xffffffff, q1, m);
        }
        if (frow == 0) {
            atomicAdd(&sumP[col], s0);
            atomicAdd(&sumP[col + 1], s1);
            atomicAdd(&sumsqP[col], q0);
            atomicAdd(&sumsqP[col + 1], q1);
        }
    }
}

// ============================================================================
// final BN normalize
// ============================================================================
__global__ void __launch_bounds__(256) k_bn_norm(const float* __restrict__ x,
                                                 float* __restrict__ out,
                                                 const float* __restrict__ gamma,
                                                 const float* __restrict__ beta,
                                                 const float* __restrict__ sumP,
                                                 const float* __restrict__ sumsqP) {
    int idx = blockIdx.x * blockDim.x + threadIdx.x;
    int base = idx * 4;
    if (base >= NN * DD) return;
    int c = base & 127;
    const float invN = 1.f / (float)NN;
    float4 v = *(const float4*)&x[base];
    float xv[4] = {v.x, v.y, v.z, v.w};
    float o[4];
#pragma unroll
    for (int j = 0; j < 4; j++) {
        float mu = sumP[c + j] * invN;
        float var = sumsqP[c + j] * invN - mu * mu;
        float rs = rsqrtf(var + EPS_BN);
        o[j] = gamma[c + j] * (xv[j] - mu) * rs + beta[c + j];
    }
    *(float4*)&out[base] = make_float4(o[0], o[1], o[2], o[3]);
}

// ============================================================================
extern "C" void kernel_launch(void* const* d_in, const int* in_sizes, int n_in,
                              void* d_out, int out_size) {
    const float* X     = (const float*)d_in[0];
    const int*   src   = (const int*)d_in[1];
    const int*   dst   = (const int*)d_in[2];
    const float* Winit = (const float*)d_in[3];
    const float* Wg    = (const float*)d_in[4];
    const float* bg    = (const float*)d_in[5];
    const float* Wr    = (const float*)d_in[6];
    const float* br    = (const float*)d_in[7];
    const float* gamma = (const float*)d_in[8];
    const float* beta  = (const float*)d_in[9];
    float* out = (float*)d_out;

    void *ph, *pagg, *ptmp, *ps, *pq, *pwt;
    cudaGetSymbolAddress(&ph, g_h);
    cudaGetSymbolAddress(&pagg, g_agg);
    cudaGetSymbolAddress(&ptmp, g_tmp);
    cudaGetSymbolAddress(&ps, g_sum);
    cudaGetSymbolAddress(&pq, g_sumsq);
    cudaGetSymbolAddress(&pwt, g_Wt);
    float* h    = (float*)ph;
    float* agg  = (float*)pagg;
    float* tmp  = (float*)ptmp;
    float* sum  = (float*)ps;
    float* sumq = (float*)pq;
    float* Wt   = (float*)pwt;

    cudaFuncSetAttribute(k_layer_fused, cudaFuncAttributeMaxDynamicSharedMemorySize,
                         SMEM_FUSED);

    const int gemmGrid = NN / 128;        // 580
    const int edgeGrid = EE / 256;        // 2320
    const int nodeGrid = (NN + 255) / 256;  // 290
    const int warpGrid = (NN * 32) / 256;   // 9280
    const int normGrid = (NN * DD / 4 + 255) / 256;  // 9280

    // prep: weights + CSR
    k_prep_w<<<6 * DD * DD / 256, 256>>>(Wg, Wr);
    k_zero<<<nodeGrid, 256>>>();
    k_hist<<<edgeGrid, 256>>>(dst);
    k_scan1<<<145, 512>>>();
    k_scan2<<<1, 256>>>();
    k_scan3<<<nodeGrid, 256>>>();
    k_fill<<<edgeGrid, 256>>>(src, dst);

    k_init_gemm<<<gemmGrid, 256>>>(X, Winit);

    const float* layerIn[NLAYERS + 1] = {h, tmp, h, tmp};  // ping-pong: in/out per layer
    for (int l = 0; l < NLAYERS; l++) {
        const float* in = layerIn[l];
        float* outBuf = (float*)layerIn[l + 1];
        if (l > 0)
            k_affine<<<1, 128>>>(sum + (l - 1) * DD, sumq + (l - 1) * DD,
                                 gamma + (l - 1) * DD, beta + (l - 1) * DD);
        k_gather<<<warpGrid, 256>>>(in);
        k_layer_fused<<<gemmGrid, 256, SMEM_FUSED>>>(
            agg, in, Wt + (l * 2 + 0) * DD * DD, Wt + (l * 2 + 1) * DD * DD,
            bg + l * DD, br + l * DD, outBuf, sum + l * DD, sumq + l * DD);
    }
    k_bn_norm<<<normGrid, 256>>>(tmp, out, gamma + 2 * DD, beta + 2 * DD,
                                 sum + 2 * DD, sumq + 2 * DD);
}

// round 6
// speedup vs baseline: 3.0110x; 1.0088x over previous
#include <cuda_runtime.h>
#include <cstdint>

#define NN 74240
#define EE 593920
#define DD 128
#define NLAYERS 3
#define EPS_BN 1e-5f

// ---------------- scratch ----------------
__device__ float g_h[NN * DD];
__device__ float g_agg[NN * DD];
__device__ float g_tmp[NN * DD];
__device__ float g_sum[NLAYERS * DD];
__device__ float g_sumsq[NLAYERS * DD];
__device__ float2 g_aff[DD];                 // per-feature BN affine (s, t)
__device__ float g_Wt[NLAYERS * 2 * DD * DD]; // transposed+rounded weights [mat][n][k]
__device__ int g_deg[NN];
__device__ int g_off[NN + 1];
__device__ int g_pos[NN];
__device__ int g_csr[EE];
__device__ int g_bsum[160];

// ---------------- helpers ----------------
__device__ __forceinline__ uint32_t smem_u32(const void* p) {
    uint32_t a;
    asm("{ .reg .u64 t; cvta.to.shared.u64 t, %1; cvt.u32.u64 %0, t; }" : "=r"(a) : "l"(p));
    return a;
}
__device__ __forceinline__ void cp16(uint32_t dst, const float* src) {
    asm volatile("cp.async.cg.shared.global [%0], [%1], 16;" :: "r"(dst), "l"(src));
}
#define CP_COMMIT() asm volatile("cp.async.commit_group;" ::: "memory")
#define CP_WAIT(n)  asm volatile("cp.async.wait_group %0;" :: "n"(n) : "memory")

__device__ __forceinline__ void ldsm_x4(uint32_t* r, uint32_t addr) {
    asm volatile("ldmatrix.sync.aligned.m8n8.x4.shared.b16 {%0,%1,%2,%3}, [%4];"
                 : "=r"(r[0]), "=r"(r[1]), "=r"(r[2]), "=r"(r[3]) : "r"(addr));
}
__device__ __forceinline__ void mma_tf32(float* c, const uint32_t* a, const uint32_t* b) {
    asm volatile(
        "mma.sync.aligned.m16n8k8.row.col.f32.tf32.tf32.f32 "
        "{%0,%1,%2,%3}, {%4,%5,%6,%7}, {%8,%9}, {%0,%1,%2,%3};"
        : "+f"(c[0]), "+f"(c[1]), "+f"(c[2]), "+f"(c[3])
        : "r"(a[0]), "r"(a[1]), "r"(a[2]), "r"(a[3]), "r"(b[0]), "r"(b[1]));
}
__device__ __forceinline__ void split_tf32(float v, uint32_t& hi, uint32_t& lo) {
    asm("cvt.rna.tf32.f32 %0, %1;" : "=r"(hi) : "f"(v));
    float r = v - __uint_as_float(hi);
    asm("cvt.rna.tf32.f32 %0, %1;" : "=r"(lo) : "f"(r));
}

// ============================================================================
// weight prep: g_Wt[mat][n][k] = round_rna_tf32( W[mat][k][n] )
// ============================================================================
__global__ void __launch_bounds__(256) k_prep_w(const float* __restrict__ Wg,
                                                const float* __restrict__ Wr) {
    int gid = blockIdx.x * 256 + threadIdx.x;    // 6 * 16384 total
    int mat = gid >> 14;
    int e = gid & 16383;
    int n = e >> 7, k = e & 127;
    int l = mat >> 1, op = mat & 1;
    const float* src = (op ? Wr : Wg) + l * DD * DD;
    float v = src[k * 128 + n];
    uint32_t u;
    asm("cvt.rna.tf32.f32 %0, %1;" : "=r"(u) : "f"(v));
    g_Wt[mat * 16384 + n * 128 + k] = __uint_as_float(u);
}

// ============================================================================
// CSR build
// ============================================================================
__global__ void __launch_bounds__(256) k_zero() {
    int i = blockIdx.x * 256 + threadIdx.x;
    if (i < NN) g_deg[i] = 0;
    if (i < NLAYERS * DD) { g_sum[i] = 0.f; g_sumsq[i] = 0.f; }
    if (i < DD) g_aff[i] = make_float2(1.f, 0.f);
}
__global__ void __launch_bounds__(256) k_hist(const int* __restrict__ dst) {
    int e = blockIdx.x * 256 + threadIdx.x;
    if (e < EE) atomicAdd(&g_deg[dst[e]], 1);
}
__global__ void __launch_bounds__(512) k_scan1() {
    __shared__ int sm[512];
    int tid = threadIdx.x;
    int i = blockIdx.x * 512 + tid;
    int v = g_deg[i];
    sm[tid] = v;
    __syncthreads();
    for (int o = 1; o < 512; o <<= 1) {
        int t = (tid >= o) ? sm[tid - o] : 0;
        __syncthreads();
        sm[tid] += t;
        __syncthreads();
    }
    g_off[i] = sm[tid] - v;
    if (tid == 511) g_bsum[blockIdx.x] = sm[511];
}
__global__ void __launch_bounds__(256) k_scan2() {
    __shared__ int sm[145];
    int tid = threadIdx.x;
    if (tid < 145) sm[tid] = g_bsum[tid];
    __syncthreads();
    if (tid == 0) {
        int run = 0;
        for (int b = 0; b < 145; b++) { int t = sm[b]; sm[b] = run; run += t; }
    }
    __syncthreads();
    if (tid < 145) g_bsum[tid] = sm[tid];
}
__global__ void __launch_bounds__(256) k_scan3() {
    int i = blockIdx.x * 256 + threadIdx.x;
    if (i < NN) {
        int o = g_off[i] + g_bsum[i >> 9];
        g_off[i] = o;
        g_pos[i] = o;
    }
    if (i == 0) g_off[NN] = EE;
}
__global__ void __launch_bounds__(256) k_fill(const int* __restrict__ src,
                                              const int* __restrict__ dst) {
    int e = blockIdx.x * 256 + threadIdx.x;
    if (e < EE) {
        int p = atomicAdd(&g_pos[dst[e]], 1);
        g_csr[p] = src[e];
    }
}

// ============================================================================
// gather: agg[d] = s * sum_{src in-edges} in[src] + deg * t  (BN folded)
// one warp per node, MLP-4 unrolled neighbor loads.
// ============================================================================
__global__ void __launch_bounds__(256) k_gather(const float* __restrict__ in) {
    int gid = blockIdx.x * 256 + threadIdx.x;
    int node = gid >> 5, lane = gid & 31;
    if (node >= NN) return;
    int beg = g_off[node], end = g_off[node + 1];
    float4 acc0 = make_float4(0.f, 0.f, 0.f, 0.f);
    float4 acc1 = make_float4(0.f, 0.f, 0.f, 0.f);
    float4 acc2 = make_float4(0.f, 0.f, 0.f, 0.f);
    float4 acc3 = make_float4(0.f, 0.f, 0.f, 0.f);
    int lo4 = lane * 4;
    for (int base = beg; base < end; base += 32) {
        int i = base + lane;
        int idx = (i < end) ? __ldg(&g_csr[i]) : 0;
        int cnt = min(32, end - base);
        int j = 0;
        for (; j + 4 <= cnt; j += 4) {
            int s0 = __shfl_sync(0xffffffff, idx, j);
            int s1 = __shfl_sync(0xffffffff, idx, j + 1);
            int s2 = __shfl_sync(0xffffffff, idx, j + 2);
            int s3 = __shfl_sync(0xffffffff, idx, j + 3);
            float4 v0 = *(const float4*)&in[s0 * 128 + lo4];
            float4 v1 = *(const float4*)&in[s1 * 128 + lo4];
            float4 v2 = *(const float4*)&in[s2 * 128 + lo4];
            float4 v3 = *(const float4*)&in[s3 * 128 + lo4];
            acc0.x += v0.x; acc0.y += v0.y; acc0.z += v0.z; acc0.w += v0.w;
            acc1.x += v1.x; acc1.y += v1.y; acc1.z += v1.z; acc1.w += v1.w;
            acc2.x += v2.x; acc2.y += v2.y; acc2.z += v2.z; acc2.w += v2.w;
            acc3.x += v3.x; acc3.y += v3.y; acc3.z += v3.z; acc3.w += v3.w;
        }
        for (; j < cnt; j++) {
            int s = __shfl_sync(0xffffffff, idx, j);
            float4 v = *(const float4*)&in[s * 128 + lo4];
            acc0.x += v.x; acc0.y += v.y; acc0.z += v.z; acc0.w += v.w;
        }
    }
    acc0.x += acc1.x + acc2.x + acc3.x;
    acc0.y += acc1.y + acc2.y + acc3.y;
    acc0.z += acc1.z + acc2.z + acc3.z;
    acc0.w += acc1.w + acc2.w + acc3.w;
    float deg = (float)(end - beg);
    float2 a0 = g_aff[lo4], a1 = g_aff[lo4 + 1];
    float2 a2 = g_aff[lo4 + 2], a3 = g_aff[lo4 + 3];
    float4 o;
    o.x = a0.x * acc0.x + deg * a0.y;
    o.y = a1.x * acc0.y + deg * a1.y;
    o.z = a2.x * acc0.z + deg * a2.y;
    o.w = a3.x * acc0.w + deg * a3.y;
    *(float4*)&g_agg[node * 128 + lo4] = o;
}

// ============================================================================
// affine from stats: s = gamma*rsqrt(var+eps), t = beta - mu*s
// ============================================================================
__global__ void k_affine(const float* __restrict__ sumP, const float* __restrict__ sumsqP,
                         const float* __restrict__ gamma, const float* __restrict__ beta) {
    int c = threadIdx.x;
    const float invN = 1.f / (float)NN;
    float mu = sumP[c] * invN;
    float var = sumsqP[c] * invN - mu * mu;
    float s = gamma[c] * rsqrtf(var + EPS_BN);
    g_aff[c] = make_float2(s, beta[c] - mu * s);
}

// ============================================================================
// init GEMM, split-tf32 (3-term compensation; numerically ~fp32):
//   g_h = X[NN,75] @ W[75,128], K padded to 80, chunks of 40.
// Fragment mapping identical to the R3-validated scalar-LDS scheme.
// ============================================================================
#define IXS 44     // Xs row stride (40 + 4 pad)
#define IWS 132    // Ws k stride

__global__ void __launch_bounds__(256) k_init_tf32(const float* __restrict__ X,
                                                   const float* __restrict__ W) {
    __shared__ float Xs[128 * IXS];
    __shared__ float Ws[40 * IWS];
    int tid = threadIdx.x;
    int lane = tid & 31;
    int wid = tid >> 5;
    int mwarp = wid & 3, nwarp = wid >> 2;
    int rowBase = blockIdx.x * 128;
    int mBase = mwarp * 32, nBase = nwarp * 64;
    int frow = lane >> 2, fcol = lane & 3;

    float acc[2][8][4];
#pragma unroll
    for (int mt = 0; mt < 2; mt++)
#pragma unroll
        for (int nt = 0; nt < 8; nt++)
#pragma unroll
            for (int j = 0; j < 4; j++) acc[mt][nt][j] = 0.f;

    for (int k0 = 0; k0 < 80; k0 += 40) {
        // X tile [128 x 40], zero-pad k >= 75
        for (int idx = tid; idx < 128 * 40; idx += 256) {
            int r = idx / 40, k = idx - r * 40;
            int gk = k0 + k;
            Xs[r * IXS + k] = (gk < 75) ? X[(rowBase + r) * 75 + gk] : 0.f;
        }
        // W tile [40 x 128], zero-pad
        for (int idx = tid; idx < 40 * 128; idx += 256) {
            int k = idx >> 7, n = idx & 127;
            int gk = k0 + k;
            Ws[k * IWS + n] = (gk < 75) ? W[gk * 128 + n] : 0.f;
        }
        __syncthreads();

#pragma unroll
        for (int kb = 0; kb < 40; kb += 8) {
            uint32_t ahi[2][4], alo[2][4];
#pragma unroll
            for (int mt = 0; mt < 2; mt++) {
                int r0 = mBase + mt * 16 + frow;
                split_tf32(Xs[r0 * IXS + kb + fcol],           ahi[mt][0], alo[mt][0]);
                split_tf32(Xs[(r0 + 8) * IXS + kb + fcol],     ahi[mt][1], alo[mt][1]);
                split_tf32(Xs[r0 * IXS + kb + fcol + 4],       ahi[mt][2], alo[mt][2]);
                split_tf32(Xs[(r0 + 8) * IXS + kb + fcol + 4], ahi[mt][3], alo[mt][3]);
            }
            uint32_t bhi[8][2], blo[8][2];
#pragma unroll
            for (int nt = 0; nt < 8; nt++) {
                int n = nBase + nt * 8 + frow;
                split_tf32(Ws[(kb + fcol) * IWS + n],     bhi[nt][0], blo[nt][0]);
                split_tf32(Ws[(kb + fcol + 4) * IWS + n], bhi[nt][1], blo[nt][1]);
            }
#pragma unroll
            for (int mt = 0; mt < 2; mt++)
#pragma unroll
                for (int nt = 0; nt < 8; nt++) {
                    mma_tf32(acc[mt][nt], ahi[mt], bhi[nt]);
                    mma_tf32(acc[mt][nt], alo[mt], bhi[nt]);
                    mma_tf32(acc[mt][nt], ahi[mt], blo[nt]);
                }
        }
        __syncthreads();
    }

#pragma unroll
    for (int mt = 0; mt < 2; mt++)
#pragma unroll
        for (int nt = 0; nt < 8; nt++) {
            int col = nBase + nt * 8 + fcol * 2;
            int r0 = rowBase + mBase + mt * 16 + frow;
            *(float2*)&g_h[r0 * 128 + col]       = make_float2(acc[mt][nt][0], acc[mt][nt][1]);
            *(float2*)&g_h[(r0 + 8) * 128 + col] = make_float2(acc[mt][nt][2], acc[mt][nt][3]);
        }
}

// ============================================================================
// Fused layer GEMM (ldmatrix tf32):
//   C = relu(A1@W1 + b1) + relu( (s*A2 + t) @ W2 + b2 )  + BN column stats
// ============================================================================
#define A2_B    18432
#define W1_B    36864
#define W2_B    55296
#define STG_B   73728
#define BIAS1_F 36864
#define BIAS2_F 36992
#define AFF_F   37120
#define SMEM_FUSED 149504

__device__ __forceinline__ void issue_chunk(uint32_t sb, int st, int c, int tid, int rowBase,
                                            const float* A1, const float* A2,
                                            const float* W1t, const float* W2t) {
    uint32_t stb = sb + st * STG_B;
    int k0 = c * 32;
#pragma unroll
    for (int i = 0; i < 4; i++) {
        int idx = i * 256 + tid;
        int r = idx >> 3, q = idx & 7;
        uint32_t soff = r * 144 + q * 16;
        int goff = k0 + q * 4;
        cp16(stb + soff,        A1 + (rowBase + r) * 128 + goff);
        cp16(stb + A2_B + soff, A2 + (rowBase + r) * 128 + goff);
        cp16(stb + W1_B + soff, W1t + r * 128 + goff);
        cp16(stb + W2_B + soff, W2t + r * 128 + goff);
    }
    CP_COMMIT();
}

__device__ __forceinline__ void compute_chunk(uint32_t sb, int st, int k0,
                                              int mBase, int nBase, int lane,
                                              const float2* affS,
                                              float acc1[2][8][4], float acc2[2][8][4]) {
    uint32_t stb = sb + st * STG_B;
    int g = lane >> 3, lr = lane & 7;
    int fcol = lane & 3;
    int arow = ((g & 1) << 3) + lr;
    int abyte = (g >> 1) << 4;
    int brow = ((g >> 1) << 3) + lr;
    int bbyte = (g & 1) << 4;

#pragma unroll
    for (int kb = 0; kb < 32; kb += 8) {
        uint32_t a1[2][4], a2[2][4];
#pragma unroll
        for (int mt = 0; mt < 2; mt++) {
            uint32_t base = stb + (uint32_t)(mBase + mt * 16 + arow) * 144 + kb * 4 + abyte;
            ldsm_x4(a1[mt], base);
            ldsm_x4(a2[mt], base + A2_B);
        }
        float2 f0 = affS[k0 + kb + fcol];
        float2 f4 = affS[k0 + kb + fcol + 4];
#pragma unroll
        for (int mt = 0; mt < 2; mt++) {
            a2[mt][0] = __float_as_uint(fmaf(f0.x, __uint_as_float(a2[mt][0]), f0.y));
            a2[mt][1] = __float_as_uint(fmaf(f0.x, __uint_as_float(a2[mt][1]), f0.y));
            a2[mt][2] = __float_as_uint(fmaf(f4.x, __uint_as_float(a2[mt][2]), f4.y));
            a2[mt][3] = __float_as_uint(fmaf(f4.x, __uint_as_float(a2[mt][3]), f4.y));
        }
        uint32_t b1[4][4], b2[4][4];
#pragma unroll
        for (int p = 0; p < 4; p++) {
            uint32_t base = stb + W1_B + (uint32_t)(nBase + p * 16 + brow) * 144 + kb * 4 + bbyte;
            ldsm_x4(b1[p], base);
            ldsm_x4(b2[p], base + (W2_B - W1_B));
        }
#pragma unroll
        for (int mt = 0; mt < 2; mt++)
#pragma unroll
            for (int p = 0; p < 4; p++) {
                mma_tf32(acc1[mt][2 * p],     a1[mt], &b1[p][0]);
                mma_tf32(acc1[mt][2 * p + 1], a1[mt], &b1[p][2]);
                mma_tf32(acc2[mt][2 * p],     a2[mt], &b2[p][0]);
                mma_tf32(acc2[mt][2 * p + 1], a2[mt], &b2[p][2]);
            }
    }
}

__global__ void __launch_bounds__(256, 1) k_layer_fused(
    const float* __restrict__ A1, const float* __restrict__ A2,
    const float* __restrict__ W1t, const float* __restrict__ W2t,
    const float* __restrict__ b1, const float* __restrict__ b2,
    float* __restrict__ C, float* __restrict__ sumP, float* __restrict__ sumsqP) {
    extern __shared__ float smf[];
    uint32_t sb = smem_u32(smf);
    int tid = threadIdx.x;
    int lane = tid & 31;
    int wid = tid >> 5;
    int mwarp = wid & 3, nwarp = wid >> 2;
    int rowBase = blockIdx.x * 128;
    int mBase = mwarp * 32, nBase = nwarp * 64;
    int frow = lane >> 2, fcol = lane & 3;

    if (tid < 128) {
        smf[BIAS1_F + tid] = b1[tid];
        smf[BIAS2_F + tid] = b2[tid];
        ((float2*)(smf + AFF_F))[tid] = g_aff[tid];
    }
    const float2* affS = (const float2*)(smf + AFF_F);

    float acc1[2][8][4], acc2[2][8][4];
#pragma unroll
    for (int mt = 0; mt < 2; mt++)
#pragma unroll
        for (int nt = 0; nt < 8; nt++)
#pragma unroll
            for (int j = 0; j < 4; j++) { acc1[mt][nt][j] = 0.f; acc2[mt][nt][j] = 0.f; }

    issue_chunk(sb, 0, 0, tid, rowBase, A1, A2, W1t, W2t);
    issue_chunk(sb, 1, 1, tid, rowBase, A1, A2, W1t, W2t);

    CP_WAIT(1); __syncthreads();
    compute_chunk(sb, 0, 0, mBase, nBase, lane, affS, acc1, acc2);
    __syncthreads();
    issue_chunk(sb, 0, 2, tid, rowBase, A1, A2, W1t, W2t);

    CP_WAIT(1); __syncthreads();
    compute_chunk(sb, 1, 32, mBase, nBase, lane, affS, acc1, acc2);
    __syncthreads();
    issue_chunk(sb, 1, 3, tid, rowBase, A1, A2, W1t, W2t);

    CP_WAIT(1); __syncthreads();
    compute_chunk(sb, 0, 64, mBase, nBase, lane, affS, acc1, acc2);
    __syncthreads();

    CP_WAIT(0); __syncthreads();
    compute_chunk(sb, 1, 96, mBase, nBase, lane, affS, acc1, acc2);

    const float* bs1 = smf + BIAS1_F;
    const float* bs2 = smf + BIAS2_F;
#pragma unroll
    for (int nt = 0; nt < 8; nt++) {
        int col = nBase + nt * 8 + fcol * 2;
        float B10 = bs1[col], B11 = bs1[col + 1];
        float B20 = bs2[col], B21 = bs2[col + 1];
        float s0 = 0.f, s1 = 0.f, q0 = 0.f, q1 = 0.f;
#pragma unroll
        for (int mt = 0; mt < 2; mt++) {
            int r0 = rowBase + mBase + mt * 16 + frow;
            int r1 = r0 + 8;
            float u0 = acc1[mt][nt][0] + B10; u0 = u0 > 0.f ? u0 : 0.f;
            float u1 = acc1[mt][nt][1] + B11; u1 = u1 > 0.f ? u1 : 0.f;
            float u2 = acc1[mt][nt][2] + B10; u2 = u2 > 0.f ? u2 : 0.f;
            float u3 = acc1[mt][nt][3] + B11; u3 = u3 > 0.f ? u3 : 0.f;
            float v0 = acc2[mt][nt][0] + B20; v0 = v0 > 0.f ? v0 : 0.f;
            float v1 = acc2[mt][nt][1] + B21; v1 = v1 > 0.f ? v1 : 0.f;
            float v2 = acc2[mt][nt][2] + B20; v2 = v2 > 0.f ? v2 : 0.f;
            float v3 = acc2[mt][nt][3] + B21; v3 = v3 > 0.f ? v3 : 0.f;
            float o0 = u0 + v0, o1 = u1 + v1, o2 = u2 + v2, o3 = u3 + v3;
            *(float2*)&C[r0 * 128 + col] = make_float2(o0, o1);
            *(float2*)&C[r1 * 128 + col] = make_float2(o2, o3);
            s0 += o0 + o2; s1 += o1 + o3;
            q0 += o0 * o0 + o2 * o2; q1 += o1 * o1 + o3 * o3;
        }
#pragma unroll
        for (int m = 4; m <= 16; m <<= 1) {
            s0 += __shfl_xor_sync(0xffffffff, s0, m);
            s1 += __shfl_xor_sync(0xffffffff, s1, m);
            q0 += __shfl_xor_sync(0xffffffff, q0, m);
            q1 += __shfl_xor_sync(0xffffffff, q1, m);
        }
        if (frow == 0) {
            atomicAdd(&sumP[col], s0);
            atomicAdd(&sumP[col + 1], s1);
            atomicAdd(&sumsqP[col], q0);
            atomicAdd(&sumsqP[col + 1], q1);
        }
    }
}

// ============================================================================
// final BN normalize
// ============================================================================
__global__ void __launch_bounds__(256) k_bn_norm(const float* __restrict__ x,
                                                 float* __restrict__ out,
                                                 const float* __restrict__ gamma,
                                                 const float* __restrict__ beta,
                                                 const float* __restrict__ sumP,
                                                 const float* __restrict__ sumsqP) {
    int idx = blockIdx.x * blockDim.x + threadIdx.x;
    int base = idx * 4;
    if (base >= NN * DD) return;
    int c = base & 127;
    const float invN = 1.f / (float)NN;
    float4 v = *(const float4*)&x[base];
    float xv[4] = {v.x, v.y, v.z, v.w};
    float o[4];
#pragma unroll
    for (int j = 0; j < 4; j++) {
        float mu = sumP[c + j] * invN;
        float var = sumsqP[c + j] * invN - mu * mu;
        float rs = rsqrtf(var + EPS_BN);
        o[j] = gamma[c + j] * (xv[j] - mu) * rs + beta[c + j];
    }
    *(float4*)&out[base] = make_float4(o[0], o[1], o[2], o[3]);
}

// ============================================================================
extern "C" void kernel_launch(void* const* d_in, const int* in_sizes, int n_in,
                              void* d_out, int out_size) {
    const float* X     = (const float*)d_in[0];
    const int*   src   = (const int*)d_in[1];
    const int*   dst   = (const int*)d_in[2];
    const float* Winit = (const float*)d_in[3];
    const float* Wg    = (const float*)d_in[4];
    const float* bg    = (const float*)d_in[5];
    const float* Wr    = (const float*)d_in[6];
    const float* br    = (const float*)d_in[7];
    const float* gamma = (const float*)d_in[8];
    const float* beta  = (const float*)d_in[9];
    float* out = (float*)d_out;

    void *ph, *pagg, *ptmp, *ps, *pq, *pwt;
    cudaGetSymbolAddress(&ph, g_h);
    cudaGetSymbolAddress(&pagg, g_agg);
    cudaGetSymbolAddress(&ptmp, g_tmp);
    cudaGetSymbolAddress(&ps, g_sum);
    cudaGetSymbolAddress(&pq, g_sumsq);
    cudaGetSymbolAddress(&pwt, g_Wt);
    float* h    = (float*)ph;
    float* agg  = (float*)pagg;
    float* tmp  = (float*)ptmp;
    float* sum  = (float*)ps;
    float* sumq = (float*)pq;
    float* Wt   = (float*)pwt;

    cudaFuncSetAttribute(k_layer_fused, cudaFuncAttributeMaxDynamicSharedMemorySize,
                         SMEM_FUSED);

    const int gemmGrid = NN / 128;          // 580
    const int edgeGrid = EE / 256;          // 2320
    const int nodeGrid = (NN + 255) / 256;  // 290
    const int warpGrid = (NN * 32) / 256;   // 9280
    const int normGrid = (NN * DD / 4 + 255) / 256;  // 9280

    // prep: weights + CSR
    k_prep_w<<<6 * DD * DD / 256, 256>>>(Wg, Wr);
    k_zero<<<nodeGrid, 256>>>();
    k_hist<<<edgeGrid, 256>>>(dst);
    k_scan1<<<145, 512>>>();
    k_scan2<<<1, 256>>>();
    k_scan3<<<nodeGrid, 256>>>();
    k_fill<<<edgeGrid, 256>>>(src, dst);

    k_init_tf32<<<gemmGrid, 256>>>(X, Winit);

    const float* layerIn[NLAYERS + 1] = {h, tmp, h, tmp};  // ping-pong
    for (int l = 0; l < NLAYERS; l++) {
        const float* in = layerIn[l];
        float* outBuf = (float*)layerIn[l + 1];
        if (l > 0)
            k_affine<<<1, 128>>>(sum + (l - 1) * DD, sumq + (l - 1) * DD,
                                 gamma + (l - 1) * DD, beta + (l - 1) * DD);
        k_gather<<<warpGrid, 256>>>(in);
        k_layer_fused<<<gemmGrid, 256, SMEM_FUSED>>>(
            agg, in, Wt + (l * 2 + 0) * DD * DD, Wt + (l * 2 + 1) * DD * DD,
            bg + l * DD, br + l * DD, outBuf, sum + l * DD, sumq + l * DD);
    }
    k_bn_norm<<<normGrid, 256>>>(tmp, out, gamma + 2 * DD, beta + 2 * DD,
                                 sum + 2 * DD, sumq + 2 * DD);
}

// round 7
// speedup vs baseline: 3.1015x; 1.0300x over previous
#include <cuda_runtime.h>
#include <cuda_fp16.h>
#include <cstdint>

#define NN 74240
#define EE 593920
#define DD 128
#define NLAYERS 3
#define EPS_BN 1e-5f

// ---------------- scratch ----------------
__device__ float g_h[NN * DD];
__device__ __half g_aggh[NN * DD];            // fp16 aggregate (10-bit mantissa ~ tf32)
__device__ float g_tmp[NN * DD];
__device__ float g_sum[NLAYERS * DD];
__device__ float g_sumsq[NLAYERS * DD];
__device__ float g_Wt[NLAYERS * 2 * DD * DD]; // transposed+rounded weights [mat][n][k]
__device__ int g_deg[NN];
__device__ int g_off[NN + 1];
__device__ int g_pos[NN];
__device__ int g_csr[EE];
__device__ int g_bsum[160];

// ---------------- helpers ----------------
__device__ __forceinline__ uint32_t smem_u32(const void* p) {
    uint32_t a;
    asm("{ .reg .u64 t; cvta.to.shared.u64 t, %1; cvt.u32.u64 %0, t; }" : "=r"(a) : "l"(p));
    return a;
}
__device__ __forceinline__ void cp16(uint32_t dst, const void* src) {
    asm volatile("cp.async.cg.shared.global [%0], [%1], 16;" :: "r"(dst), "l"(src));
}
#define CP_COMMIT() asm volatile("cp.async.commit_group;" ::: "memory")
#define CP_WAIT(n)  asm volatile("cp.async.wait_group %0;" :: "n"(n) : "memory")

__device__ __forceinline__ void ldsm_x4(uint32_t* r, uint32_t addr) {
    asm volatile("ldmatrix.sync.aligned.m8n8.x4.shared.b16 {%0,%1,%2,%3}, [%4];"
                 : "=r"(r[0]), "=r"(r[1]), "=r"(r[2]), "=r"(r[3]) : "r"(addr));
}
__device__ __forceinline__ void mma_tf32(float* c, const uint32_t* a, const uint32_t* b) {
    asm volatile(
        "mma.sync.aligned.m16n8k8.row.col.f32.tf32.tf32.f32 "
        "{%0,%1,%2,%3}, {%4,%5,%6,%7}, {%8,%9}, {%0,%1,%2,%3};"
        : "+f"(c[0]), "+f"(c[1]), "+f"(c[2]), "+f"(c[3])
        : "r"(a[0]), "r"(a[1]), "r"(a[2]), "r"(a[3]), "r"(b[0]), "r"(b[1]));
}
__device__ __forceinline__ void split_tf32(float v, uint32_t& hi, uint32_t& lo) {
    asm("cvt.rna.tf32.f32 %0, %1;" : "=r"(hi) : "f"(v));
    float r = v - __uint_as_float(hi);
    asm("cvt.rna.tf32.f32 %0, %1;" : "=r"(lo) : "f"(r));
}

// ============================================================================
// weight prep: g_Wt[mat][n][k] = round_rna_tf32( W[mat][k][n] )
// ============================================================================
__global__ void __launch_bounds__(256) k_prep_w(const float* __restrict__ Wg,
                                                const float* __restrict__ Wr) {
    int gid = blockIdx.x * 256 + threadIdx.x;
    int mat = gid >> 14;
    int e = gid & 16383;
    int n = e >> 7, k = e & 127;
    int l = mat >> 1, op = mat & 1;
    const float* src = (op ? Wr : Wg) + l * DD * DD;
    float v = src[k * 128 + n];
    uint32_t u;
    asm("cvt.rna.tf32.f32 %0, %1;" : "=r"(u) : "f"(v));
    g_Wt[mat * 16384 + n * 128 + k] = __uint_as_float(u);
}

// ============================================================================
// CSR build
// ============================================================================
__global__ void __launch_bounds__(256) k_zero() {
    int i = blockIdx.x * 256 + threadIdx.x;
    if (i < NN) g_deg[i] = 0;
    if (i < NLAYERS * DD) { g_sum[i] = 0.f; g_sumsq[i] = 0.f; }
}
__global__ void __launch_bounds__(256) k_hist(const int* __restrict__ dst) {
    int e = blockIdx.x * 256 + threadIdx.x;
    if (e < EE) atomicAdd(&g_deg[dst[e]], 1);
}
__global__ void __launch_bounds__(512) k_scan1() {
    __shared__ int ws[16];
    int tid = threadIdx.x;
    int lane = tid & 31, w = tid >> 5;
    int i = blockIdx.x * 512 + tid;
    int v = g_deg[i];
    int x = v;
#pragma unroll
    for (int o = 1; o < 32; o <<= 1) {
        int t = __shfl_up_sync(0xffffffff, x, o);
        if (lane >= o) x += t;
    }
    if (lane == 31) ws[w] = x;
    __syncthreads();
    if (w == 0) {
        int y = (lane < 16) ? ws[lane] : 0;
#pragma unroll
        for (int o = 1; o < 16; o <<= 1) {
            int t = __shfl_up_sync(0xffffffff, y, o);
            if (lane >= o) y += t;
        }
        if (lane < 16) ws[lane] = y;
    }
    __syncthreads();
    int base = (w > 0) ? ws[w - 1] : 0;
    g_off[i] = base + x - v;
    if (tid == 511) g_bsum[blockIdx.x] = base + x;
}
__global__ void __launch_bounds__(256) k_scan2() {
    __shared__ int sm[145];
    int tid = threadIdx.x;
    if (tid < 145) sm[tid] = g_bsum[tid];
    __syncthreads();
    if (tid == 0) {
        int run = 0;
        for (int b = 0; b < 145; b++) { int t = sm[b]; sm[b] = run; run += t; }
    }
    __syncthreads();
    if (tid < 145) g_bsum[tid] = sm[tid];
}
__global__ void __launch_bounds__(256) k_scan3() {
    int i = blockIdx.x * 256 + threadIdx.x;
    if (i < NN) {
        int o = g_off[i] + g_bsum[i >> 9];
        g_off[i] = o;
        g_pos[i] = o;
    }
    if (i == 0) g_off[NN] = EE;
}
__global__ void __launch_bounds__(256) k_fill(const int* __restrict__ src,
                                              const int* __restrict__ dst) {
    int e = blockIdx.x * 256 + threadIdx.x;
    if (e < EE) {
        int p = atomicAdd(&g_pos[dst[e]], 1);
        g_csr[p] = src[e];
    }
}

// ============================================================================
// gather: aggh[d] = fp16( s * sum_{src} in[src] + deg * t )   (BN affine folded,
// affine computed per-block from prev-layer stats)
// ============================================================================
__global__ void __launch_bounds__(256) k_gather(const float* __restrict__ in,
                                                const float* __restrict__ sumP,
                                                const float* __restrict__ sumsqP,
                                                const float* __restrict__ gamma,
                                                const float* __restrict__ beta,
                                                int useAff) {
    __shared__ float2 aff[128];
    int tid = threadIdx.x;
    if (tid < 128) {
        float2 a = make_float2(1.f, 0.f);
        if (useAff) {
            const float invN = 1.f / (float)NN;
            float mu = sumP[tid] * invN;
            float var = sumsqP[tid] * invN - mu * mu;
            float s = gamma[tid] * rsqrtf(var + EPS_BN);
            a = make_float2(s, beta[tid] - mu * s);
        }
        aff[tid] = a;
    }
    __syncthreads();

    int gid = blockIdx.x * 256 + tid;
    int node = gid >> 5, lane = gid & 31;
    if (node >= NN) return;
    int beg = g_off[node], end = g_off[node + 1];
    float4 acc0 = make_float4(0.f, 0.f, 0.f, 0.f);
    float4 acc1 = make_float4(0.f, 0.f, 0.f, 0.f);
    float4 acc2 = make_float4(0.f, 0.f, 0.f, 0.f);
    float4 acc3 = make_float4(0.f, 0.f, 0.f, 0.f);
    int lo4 = lane * 4;
    for (int base = beg; base < end; base += 32) {
        int i = base + lane;
        int idx = (i < end) ? __ldg(&g_csr[i]) : 0;
        int cnt = min(32, end - base);
        int j = 0;
        for (; j + 4 <= cnt; j += 4) {
            int s0 = __shfl_sync(0xffffffff, idx, j);
            int s1 = __shfl_sync(0xffffffff, idx, j + 1);
            int s2 = __shfl_sync(0xffffffff, idx, j + 2);
            int s3 = __shfl_sync(0xffffffff, idx, j + 3);
            float4 v0 = *(const float4*)&in[s0 * 128 + lo4];
            float4 v1 = *(const float4*)&in[s1 * 128 + lo4];
            float4 v2 = *(const float4*)&in[s2 * 128 + lo4];
            float4 v3 = *(const float4*)&in[s3 * 128 + lo4];
            acc0.x += v0.x; acc0.y += v0.y; acc0.z += v0.z; acc0.w += v0.w;
            acc1.x += v1.x; acc1.y += v1.y; acc1.z += v1.z; acc1.w += v1.w;
            acc2.x += v2.x; acc2.y += v2.y; acc2.z += v2.z; acc2.w += v2.w;
            acc3.x += v3.x; acc3.y += v3.y; acc3.z += v3.z; acc3.w += v3.w;
        }
        for (; j < cnt; j++) {
            int s = __shfl_sync(0xffffffff, idx, j);
            float4 v = *(const float4*)&in[s * 128 + lo4];
            acc0.x += v.x; acc0.y += v.y; acc0.z += v.z; acc0.w += v.w;
        }
    }
    acc0.x += acc1.x + acc2.x + acc3.x;
    acc0.y += acc1.y + acc2.y + acc3.y;
    acc0.z += acc1.z + acc2.z + acc3.z;
    acc0.w += acc1.w + acc2.w + acc3.w;
    float deg = (float)(end - beg);
    float2 a0 = aff[lo4], a1 = aff[lo4 + 1], a2 = aff[lo4 + 2], a3 = aff[lo4 + 3];
    float o0 = a0.x * acc0.x + deg * a0.y;
    float o1 = a1.x * acc0.y + deg * a1.y;
    float o2 = a2.x * acc0.z + deg * a2.y;
    float o3 = a3.x * acc0.w + deg * a3.y;
    __half2 p0 = __floats2half2_rn(o0, o1);
    __half2 p1 = __floats2half2_rn(o2, o3);
    uint2 pk;
    pk.x = *(uint32_t*)&p0;
    pk.y = *(uint32_t*)&p1;
    *(uint2*)&g_aggh[node * 128 + lo4] = pk;
}

// ============================================================================
// init GEMM, split-tf32 (3-term compensation; ~fp32): g_h = X @ W
// ============================================================================
#define IXS 44
#define IWS 132

__global__ void __launch_bounds__(256) k_init_tf32(const float* __restrict__ X,
                                                   const float* __restrict__ W) {
    __shared__ float Xs[128 * IXS];
    __shared__ float Ws[40 * IWS];
    int tid = threadIdx.x;
    int lane = tid & 31;
    int wid = tid >> 5;
    int mwarp = wid & 3, nwarp = wid >> 2;
    int rowBase = blockIdx.x * 128;
    int mBase = mwarp * 32, nBase = nwarp * 64;
    int frow = lane >> 2, fcol = lane & 3;

    float acc[2][8][4];
#pragma unroll
    for (int mt = 0; mt < 2; mt++)
#pragma unroll
        for (int nt = 0; nt < 8; nt++)
#pragma unroll
            for (int j = 0; j < 4; j++) acc[mt][nt][j] = 0.f;

    for (int k0 = 0; k0 < 80; k0 += 40) {
        for (int idx = tid; idx < 128 * 40; idx += 256) {
            int r = idx / 40, k = idx - r * 40;
            int gk = k0 + k;
            Xs[r * IXS + k] = (gk < 75) ? X[(rowBase + r) * 75 + gk] : 0.f;
        }
        for (int idx = tid; idx < 40 * 128; idx += 256) {
            int k = idx >> 7, n = idx & 127;
            int gk = k0 + k;
            Ws[k * IWS + n] = (gk < 75) ? W[gk * 128 + n] : 0.f;
        }
        __syncthreads();

#pragma unroll
        for (int kb = 0; kb < 40; kb += 8) {
            uint32_t ahi[2][4], alo[2][4];
#pragma unroll
            for (int mt = 0; mt < 2; mt++) {
                int r0 = mBase + mt * 16 + frow;
                split_tf32(Xs[r0 * IXS + kb + fcol],           ahi[mt][0], alo[mt][0]);
                split_tf32(Xs[(r0 + 8) * IXS + kb + fcol],     ahi[mt][1], alo[mt][1]);
                split_tf32(Xs[r0 * IXS + kb + fcol + 4],       ahi[mt][2], alo[mt][2]);
                split_tf32(Xs[(r0 + 8) * IXS + kb + fcol + 4], ahi[mt][3], alo[mt][3]);
            }
            uint32_t bhi[8][2], blo[8][2];
#pragma unroll
            for (int nt = 0; nt < 8; nt++) {
                int n = nBase + nt * 8 + frow;
                split_tf32(Ws[(kb + fcol) * IWS + n],     bhi[nt][0], blo[nt][0]);
                split_tf32(Ws[(kb + fcol + 4) * IWS + n], bhi[nt][1], blo[nt][1]);
            }
#pragma unroll
            for (int mt = 0; mt < 2; mt++)
#pragma unroll
                for (int nt = 0; nt < 8; nt++) {
                    mma_tf32(acc[mt][nt], ahi[mt], bhi[nt]);
                    mma_tf32(acc[mt][nt], alo[mt], bhi[nt]);
                    mma_tf32(acc[mt][nt], ahi[mt], blo[nt]);
                }
        }
        __syncthreads();
    }

#pragma unroll
    for (int mt = 0; mt < 2; mt++)
#pragma unroll
        for (int nt = 0; nt < 8; nt++) {
            int col = nBase + nt * 8 + fcol * 2;
            int r0 = rowBase + mBase + mt * 16 + frow;
            *(float2*)&g_h[r0 * 128 + col]       = make_float2(acc[mt][nt][0], acc[mt][nt][1]);
            *(float2*)&g_h[(r0 + 8) * 128 + col] = make_float2(acc[mt][nt][2], acc[mt][nt][3]);
        }
}

// ============================================================================
// Fused layer GEMM:  C = relu(A1@W1 + b1) + relu( (s*A2 + t) @ W2 + b2 ) + stats
// A1 = fp16 agg [128 x 32h per chunk, stride 80B]; A2/W fp32 [stride 144B].
// 2-stage cp.async pipeline, 4 k-chunks of 32.
// ============================================================================
#define A1_B    0
#define A2_B    10240
#define W1_B    28672
#define W2_B    47104
#define STG_B   65536
#define BIAS1_F (2 * STG_B / 4)            // float index 32768
#define BIAS2_F (BIAS1_F + 128)
#define AFF_F   (BIAS2_F + 128)
#define SMEM_FUSED (2 * STG_B + 512 + 512 + 1024)

__device__ __forceinline__ void issue_chunk(uint32_t sb, int st, int c, int tid, int rowBase,
                                            const __half* A1h, const float* A2,
                                            const float* W1t, const float* W2t) {
    uint32_t stb = sb + st * STG_B;
    int k0 = c * 32;
    // A1: fp16, 512 x cp16 (4 per row of 64B)
#pragma unroll
    for (int i = 0; i < 2; i++) {
        int idx = i * 256 + tid;
        int r = idx >> 2, q = idx & 3;
        cp16(stb + A1_B + r * 80 + q * 16, A1h + (rowBase + r) * 128 + k0 + q * 8);
    }
    // A2, W1, W2: fp32, 1024 x cp16 each
#pragma unroll
    for (int i = 0; i < 4; i++) {
        int idx = i * 256 + tid;
        int r = idx >> 3, q = idx & 7;
        uint32_t soff = r * 144 + q * 16;
        int goff = k0 + q * 4;
        cp16(stb + A2_B + soff, A2 + (rowBase + r) * 128 + goff);
        cp16(stb + W1_B + soff, W1t + r * 128 + goff);
        cp16(stb + W2_B + soff, W2t + r * 128 + goff);
    }
    CP_COMMIT();
}

__device__ __forceinline__ void compute_chunk(const char* smc, uint32_t sb, int st, int k0,
                                              int mBase, int nBase, int lane,
                                              const float2* affS,
                                              float acc1[2][8][4], float acc2[2][8][4]) {
    uint32_t stb = sb + st * STG_B;
    const __half* As1 = (const __half*)(smc + st * STG_B + A1_B);
    int g = lane >> 3, lr = lane & 7;
    int frow = lane >> 2, fcol = lane & 3;
    int arow = ((g & 1) << 3) + lr;
    int abyte = (g >> 1) << 4;
    int brow = ((g >> 1) << 3) + lr;
    int bbyte = (g & 1) << 4;

#pragma unroll
    for (int kb = 0; kb < 32; kb += 8) {
        // A1 fragments: scalar fp16 loads (exact in tf32)
        uint32_t a1[2][4];
#pragma unroll
        for (int mt = 0; mt < 2; mt++) {
            int r0 = mBase + mt * 16 + frow;
            a1[mt][0] = __float_as_uint(__half2float(As1[r0 * 40 + kb + fcol]));
            a1[mt][1] = __float_as_uint(__half2float(As1[(r0 + 8) * 40 + kb + fcol]));
            a1[mt][2] = __float_as_uint(__half2float(As1[r0 * 40 + kb + fcol + 4]));
            a1[mt][3] = __float_as_uint(__half2float(As1[(r0 + 8) * 40 + kb + fcol + 4]));
        }
        // A2 fragments via ldmatrix + affine
        uint32_t a2[2][4];
#pragma unroll
        for (int mt = 0; mt < 2; mt++) {
            uint32_t base = stb + A2_B + (uint32_t)(mBase + mt * 16 + arow) * 144 + kb * 4 + abyte;
            ldsm_x4(a2[mt], base);
        }
        float2 f0 = affS[k0 + kb + fcol];
        float2 f4 = affS[k0 + kb + fcol + 4];
#pragma unroll
        for (int mt = 0; mt < 2; mt++) {
            a2[mt][0] = __float_as_uint(fmaf(f0.x, __uint_as_float(a2[mt][0]), f0.y));
            a2[mt][1] = __float_as_uint(fmaf(f0.x, __uint_as_float(a2[mt][1]), f0.y));
            a2[mt][2] = __float_as_uint(fmaf(f4.x, __uint_as_float(a2[mt][2]), f4.y));
            a2[mt][3] = __float_as_uint(fmaf(f4.x, __uint_as_float(a2[mt][3]), f4.y));
        }
        uint32_t b1[4][4], b2[4][4];
#pragma unroll
        for (int p = 0; p < 4; p++) {
            uint32_t base = stb + W1_B + (uint32_t)(nBase + p * 16 + brow) * 144 + kb * 4 + bbyte;
            ldsm_x4(b1[p], base);
            ldsm_x4(b2[p], base + (W2_B - W1_B));
        }
#pragma unroll
        for (int mt = 0; mt < 2; mt++)
#pragma unroll
            for (int p = 0; p < 4; p++) {
                mma_tf32(acc1[mt][2 * p],     a1[mt], &b1[p][0]);
                mma_tf32(acc1[mt][2 * p + 1], a1[mt], &b1[p][2]);
                mma_tf32(acc2[mt][2 * p],     a2[mt], &b2[p][0]);
                mma_tf32(acc2[mt][2 * p + 1], a2[mt], &b2[p][2]);
            }
    }
}

__global__ void __launch_bounds__(256, 1) k_layer_fused(
    const __half* __restrict__ A1h, const float* __restrict__ A2,
    const float* __restrict__ W1t, const float* __restrict__ W2t,
    const float* __restrict__ b1, const float* __restrict__ b2,
    const float* __restrict__ sumPrev, const float* __restrict__ sumsqPrev,
    const float* __restrict__ gammaPrev, const float* __restrict__ betaPrev, int useAff,
    float* __restrict__ C, float* __restrict__ sumP, float* __restrict__ sumsqP) {
    extern __shared__ char smc[];
    float* smf = (float*)smc;
    uint32_t sb = smem_u32(smc);
    int tid = threadIdx.x;
    int lane = tid & 31;
    int wid = tid >> 5;
    int mwarp = wid & 3, nwarp = wid >> 2;
    int rowBase = blockIdx.x * 128;
    int mBase = mwarp * 32, nBase = nwarp * 64;
    int frow = lane >> 2, fcol = lane & 3;

    if (tid < 128) {
        smf[BIAS1_F + tid] = b1[tid];
        smf[BIAS2_F + tid] = b2[tid];
        float2 a = make_float2(1.f, 0.f);
        if (useAff) {
            const float invN = 1.f / (float)NN;
            float mu = sumPrev[tid] * invN;
            float var = sumsqPrev[tid] * invN - mu * mu;
            float s = gammaPrev[tid] * rsqrtf(var + EPS_BN);
            a = make_float2(s, betaPrev[tid] - mu * s);
        }
        ((float2*)(smf + AFF_F))[tid] = a;
    }
    const float2* affS = (const float2*)(smf + AFF_F);

    float acc1[2][8][4], acc2[2][8][4];
#pragma unroll
    for (int mt = 0; mt < 2; mt++)
#pragma unroll
        for (int nt = 0; nt < 8; nt++)
#pragma unroll
            for (int j = 0; j < 4; j++) { acc1[mt][nt][j] = 0.f; acc2[mt][nt][j] = 0.f; }

    issue_chunk(sb, 0, 0, tid, rowBase, A1h, A2, W1t, W2t);
    issue_chunk(sb, 1, 1, tid, rowBase, A1h, A2, W1t, W2t);

    CP_WAIT(1); __syncthreads();
    compute_chunk(smc, sb, 0, 0, mBase, nBase, lane, affS, acc1, acc2);
    __syncthreads();
    issue_chunk(sb, 0, 2, tid, rowBase, A1h, A2, W1t, W2t);

    CP_WAIT(1); __syncthreads();
    compute_chunk(smc, sb, 1, 32, mBase, nBase, lane, affS, acc1, acc2);
    __syncthreads();
    issue_chunk(sb, 1, 3, tid, rowBase, A1h, A2, W1t, W2t);

    CP_WAIT(1); __syncthreads();
    compute_chunk(smc, sb, 0, 64, mBase, nBase, lane, affS, acc1, acc2);
    __syncthreads();

    CP_WAIT(0); __syncthreads();
    compute_chunk(smc, sb, 1, 96, mBase, nBase, lane, affS, acc1, acc2);

    const float* bs1 = smf + BIAS1_F;
    const float* bs2 = smf + BIAS2_F;
#pragma unroll
    for (int nt = 0; nt < 8; nt++) {
        int col = nBase + nt * 8 + fcol * 2;
        float B10 = bs1[col], B11 = bs1[col + 1];
        float B20 = bs2[col], B21 = bs2[col + 1];
        float s0 = 0.f, s1 = 0.f, q0 = 0.f, q1 = 0.f;
#pragma unroll
        for (int mt = 0; mt < 2; mt++) {
            int r0 = rowBase + mBase + mt * 16 + frow;
            int r1 = r0 + 8;
            float u0 = acc1[mt][nt][0] + B10; u0 = u0 > 0.f ? u0 : 0.f;
            float u1 = acc1[mt][nt][1] + B11; u1 = u1 > 0.f ? u1 : 0.f;
            float u2 = acc1[mt][nt][2] + B10; u2 = u2 > 0.f ? u2 : 0.f;
            float u3 = acc1[mt][nt][3] + B11; u3 = u3 > 0.f ? u3 : 0.f;
            float v0 = acc2[mt][nt][0] + B20; v0 = v0 > 0.f ? v0 : 0.f;
            float v1 = acc2[mt][nt][1] + B21; v1 = v1 > 0.f ? v1 : 0.f;
            float v2 = acc2[mt][nt][2] + B20; v2 = v2 > 0.f ? v2 : 0.f;
            float v3 = acc2[mt][nt][3] + B21; v3 = v3 > 0.f ? v3 : 0.f;
            float o0 = u0 + v0, o1 = u1 + v1, o2 = u2 + v2, o3 = u3 + v3;
            *(float2*)&C[r0 * 128 + col] = make_float2(o0, o1);
            *(float2*)&C[r1 * 128 + col] = make_float2(o2, o3);
            s0 += o0 + o2; s1 += o1 + o3;
            q0 += o0 * o0 + o2 * o2; q1 += o1 * o1 + o3 * o3;
        }
#pragma unroll
        for (int m = 4; m <= 16; m <<= 1) {
            s0 += __shfl_xor_sync(0xffffffff, s0, m);
            s1 += __shfl_xor_sync(0xffffffff, s1, m);
            q0 += __shfl_xor_sync(0xffffffff, q0, m);
            q1 += __shfl_xor_sync(0xffffffff, q1, m);
        }
        if (frow == 0) {
            atomicAdd(&sumP[col], s0);
            atomicAdd(&sumP[col + 1], s1);
            atomicAdd(&sumsqP[col], q0);
            atomicAdd(&sumsqP[col + 1], q1);
        }
    }
}

// ============================================================================
// final BN normalize
// ============================================================================
__global__ void __launch_bounds__(256) k_bn_norm(const float* __restrict__ x,
                                                 float* __restrict__ out,
                                                 const float* __restrict__ gamma,
                                                 const float* __restrict__ beta,
                                                 const float* __restrict__ sumP,
                                                 const float* __restrict__ sumsqP) {
    int idx = blockIdx.x * blockDim.x + threadIdx.x;
    int base = idx * 4;
    if (base >= NN * DD) return;
    int c = base & 127;
    const float invN = 1.f / (float)NN;
    float4 v = *(const float4*)&x[base];
    float xv[4] = {v.x, v.y, v.z, v.w};
    float o[4];
#pragma unroll
    for (int j = 0; j < 4; j++) {
        float mu = sumP[c + j] * invN;
        float var = sumsqP[c + j] * invN - mu * mu;
        float rs = rsqrtf(var + EPS_BN);
        o[j] = gamma[c + j] * (xv[j] - mu) * rs + beta[c + j];
    }
    *(float4*)&out[base] = make_float4(o[0], o[1], o[2], o[3]);
}

// ============================================================================
extern "C" void kernel_launch(void* const* d_in, const int* in_sizes, int n_in,
                              void* d_out, int out_size) {
    const float* X     = (const float*)d_in[0];
    const int*   src   = (const int*)d_in[1];
    const int*   dst   = (const int*)d_in[2];
    const float* Winit = (const float*)d_in[3];
    const float* Wg    = (const float*)d_in[4];
    const float* bg    = (const float*)d_in[5];
    const float* Wr    = (const float*)d_in[6];
    const float* br    = (const float*)d_in[7];
    const float* gamma = (const float*)d_in[8];
    const float* beta  = (const float*)d_in[9];
    float* out = (float*)d_out;

    void *ph, *pagg, *ptmp, *ps, *pq, *pwt;
    cudaGetSymbolAddress(&ph, g_h);
    cudaGetSymbolAddress(&pagg, g_aggh);
    cudaGetSymbolAddress(&ptmp, g_tmp);
    cudaGetSymbolAddress(&ps, g_sum);
    cudaGetSymbolAddress(&pq, g_sumsq);
    cudaGetSymbolAddress(&pwt, g_Wt);
    float*  h    = (float*)ph;
    __half* aggh = (__half*)pagg;
    float*  tmp  = (float*)ptmp;
    float*  sum  = (float*)ps;
    float*  sumq = (float*)pq;
    float*  Wt   = (float*)pwt;

    cudaFuncSetAttribute(k_layer_fused, cudaFuncAttributeMaxDynamicSharedMemorySize,
                         SMEM_FUSED);

    const int gemmGrid = NN / 128;
    const int edgeGrid = EE / 256;
    const int nodeGrid = (NN + 255) / 256;
    const int warpGrid = (NN * 32) / 256;
    const int normGrid = (NN * DD / 4 + 255) / 256;

    k_prep_w<<<6 * DD * DD / 256, 256>>>(Wg, Wr);
    k_zero<<<nodeGrid, 256>>>();
    k_hist<<<edgeGrid, 256>>>(dst);
    k_scan1<<<145, 512>>>();
    k_scan2<<<1, 256>>>();
    k_scan3<<<nodeGrid, 256>>>();
    k_fill<<<edgeGrid, 256>>>(src, dst);

    k_init_tf32<<<gemmGrid, 256>>>(X, Winit);

    const float* layerIn[NLAYERS + 1] = {h, tmp, h, tmp};
    for (int l = 0; l < NLAYERS; l++) {
        const float* in = layerIn[l];
        float* outBuf = (float*)layerIn[l + 1];
        const float* sPrev = sum + (l - 1) * DD;
        const float* qPrev = sumq + (l - 1) * DD;
        const float* gPrev = gamma + (l - 1) * DD;
        const float* bPrev = beta + (l - 1) * DD;
        int useAff = (l > 0) ? 1 : 0;
        if (!useAff) { sPrev = sum; qPrev = sumq; gPrev = gamma; bPrev = beta; }
        k_gather<<<warpGrid, 256>>>(in, sPrev, qPrev, gPrev, bPrev, useAff);
        k_layer_fused<<<gemmGrid, 256, SMEM_FUSED>>>(
            aggh, in, Wt + (l * 2 + 0) * DD * DD, Wt + (l * 2 + 1) * DD * DD,
            bg + l * DD, br + l * DD,
            sPrev, qPrev, gPrev, bPrev, useAff,
            outBuf, sum + l * DD, sumq + l * DD);
    }
    k_bn_norm<<<normGrid, 256>>>(tmp, out, gamma + 2 * DD, beta + 2 * DD,
                                 sum + 2 * DD, sumq + 2 * DD);
}